// round 10
// baseline (speedup 1.0000x reference)
#include <cuda_runtime.h>

// ---------------- problem constants ----------------
#define KDIM 128          // feature / hidden / out dim
#define TM   128          // edges (rows) per CTA tile
#define SA   132          // padded smem stride (floats)
#define NTHREADS 256
#define MAX_NODES 100000

// ---------------- device scratch (no cudaMalloc allowed) ----------------
__device__ float g_wT[4][KDIM * KDIM];            // k-major weights: 0=w_efeat,1=w_src,2=w_dst,3=w2
__device__ float g_proj[2][MAX_NODES * KDIM];     // 0 = mlp_src, 1 = mlp_dst(+b1)

typedef unsigned long long u64;

// ---------------- f32x2 packed helpers (Blackwell sm_103a) ----------------
__device__ __forceinline__ u64 dup2(float x) {
    u64 r; asm("mov.b64 %0,{%1,%1};" : "=l"(r) : "f"(x)); return r;
}
__device__ __forceinline__ void fma2(u64 &d, u64 a, u64 b) {
    asm("fma.rn.f32x2 %0,%1,%2,%0;" : "+l"(d) : "l"(a), "l"(b));
}
__device__ __forceinline__ float2 upk(u64 v) {
    float2 f; asm("mov.b64 {%0,%1},%2;" : "=f"(f.x), "=f"(f.y) : "l"(v)); return f;
}

// ---------------- weight pre-transpose: g_wT[b][k*128+n] = w[n*128+k] ----------------
__global__ void wtranspose_kernel(const float* __restrict__ w0, const float* __restrict__ w1,
                                  const float* __restrict__ w2_, const float* __restrict__ w3) {
    const float* src = (blockIdx.x == 0) ? w0 : (blockIdx.x == 1) ? w1 : (blockIdx.x == 2) ? w2_ : w3;
    float* dst = g_wT[blockIdx.x];
    for (int v = threadIdx.x; v < KDIM * KDIM; v += blockDim.x) {
        int k = v & (KDIM - 1);
        int n = v >> 7;
        dst[k * KDIM + n] = src[n * KDIM + k];
    }
}

// ---------------- smem loaders ----------------
// Load a [TM x 128] row-major tile transposed into As[k][m] (stride SA), zero-pad OOB rows.
__device__ __forceinline__ void load_A_transposed(float* As, const float* __restrict__ feat,
                                                  int base, int limit, int t) {
    int lane = t & 31, warp = t >> 5;
    int q  = lane >> 3;   // 0..3  (row offset)
    int kc = lane & 7;    // 0..7  (float4 chunk within 8)
#pragma unroll
    for (int i = 0; i < 16; i++) {
        int m     = q + 4 * warp + 32 * (i & 3);   // 0..127
        int chunk = kc + 8 * (i >> 2);             // 0..31
        int row   = base + m;
        float4 v = make_float4(0.f, 0.f, 0.f, 0.f);
        if (row < limit)
            v = *(const float4*)(feat + (size_t)row * KDIM + chunk * 4);
        int k = chunk * 4;
        As[(k + 0) * SA + m] = v.x;
        As[(k + 1) * SA + m] = v.y;
        As[(k + 2) * SA + m] = v.z;
        As[(k + 3) * SA + m] = v.w;
    }
}

// Copy pre-transposed weights (dense, stride 128) into padded smem (stride SA).
__device__ __forceinline__ void copy_B(float* Bs, const float* __restrict__ wT, int t) {
#pragma unroll
    for (int i = 0; i < 16; i++) {
        int v = t + i * NTHREADS;
        int k = v >> 5;
        int n = (v & 31) * 4;
        *(float4*)(Bs + k * SA + n) = *(const float4*)(wT + k * KDIM + n);
    }
}

// ---------------- core GEMM: acc[m][n] += sum_k As[k][m] * Bs[k][n], 8x8 per thread ----------------
__device__ __forceinline__ void gemm128(const float* As, const float* Bs,
                                        u64 acc[32], int row0, int col0) {
#pragma unroll 2
    for (int k = 0; k < KDIM; k++) {
        const float* ap = As + k * SA + row0;
        float4 a0 = *(const float4*)ap;
        float4 a1 = *(const float4*)(ap + 4);
        const u64* bp = (const u64*)(Bs + k * SA + col0);
        u64 b0 = bp[0], b1 = bp[1], b2 = bp[2], b3 = bp[3];
        float a[8] = {a0.x, a0.y, a0.z, a0.w, a1.x, a1.y, a1.z, a1.w};
#pragma unroll
        for (int r = 0; r < 8; r++) {
            u64 ad = dup2(a[r]);
            fma2(acc[r * 4 + 0], ad, b0);
            fma2(acc[r * 4 + 1], ad, b1);
            fma2(acc[r * 4 + 2], ad, b2);
            fma2(acc[r * 4 + 3], ad, b3);
        }
    }
}

// ---------------- node projection kernel: g_proj[which] = feat @ wT (+bias) ----------------
__global__ void __launch_bounds__(NTHREADS, 1)
node_kernel(const float* __restrict__ feat, const float* __restrict__ bias,
            int N, int which, int wsel) {
    extern __shared__ float sm[];
    float* As = sm;
    float* Bs = sm + KDIM * SA;
    int t = threadIdx.x;
    int n0 = blockIdx.x * TM;

    load_A_transposed(As, feat, n0, N, t);
    copy_B(Bs, g_wT[wsel], t);
    __syncthreads();

    int tx = t & 15, ty = t >> 4;
    int row0 = ty * 8, col0 = tx * 8;

    u64 acc[32];
#pragma unroll
    for (int i = 0; i < 32; i++) acc[i] = 0ull;
    gemm128(As, Bs, acc, row0, col0);

    float bb[8];
#pragma unroll
    for (int c = 0; c < 8; c++) bb[c] = bias ? __ldg(bias + col0 + c) : 0.f;

    float* outp = g_proj[which];
#pragma unroll
    for (int r = 0; r < 8; r++) {
        int m = n0 + row0 + r;
        if (m < N) {
            float o[8];
#pragma unroll
            for (int c2 = 0; c2 < 4; c2++) {
                float2 f = upk(acc[r * 4 + c2]);
                o[c2 * 2 + 0] = f.x + bb[c2 * 2 + 0];
                o[c2 * 2 + 1] = f.y + bb[c2 * 2 + 1];
            }
            float* po = outp + (size_t)m * KDIM + col0;
            *(float4*)(po + 0) = make_float4(o[0], o[1], o[2], o[3]);
            *(float4*)(po + 4) = make_float4(o[4], o[5], o[6], o[7]);
        }
    }
}

// ---------------- fused edge kernel: GEMM1 + gather + SiLU + GEMM2 + LayerNorm ----------------
__global__ void __launch_bounds__(NTHREADS, 1)
edge_kernel(const float* __restrict__ efeat,
            const int* __restrict__ srcidx, const int* __restrict__ dstidx,
            const float* __restrict__ b2, const float* __restrict__ gamma,
            const float* __restrict__ beta,
            float* __restrict__ out, int E) {
    extern __shared__ float sm[];
    float* As  = sm;
    float* Bs1 = sm + 1 * KDIM * SA;
    float* Bs2 = sm + 2 * KDIM * SA;
    float* tail = sm + 3 * KDIM * SA;
    int*   sidx = (int*)tail;
    int*   didx = sidx + TM;
    float* b2s  = (float*)(didx + TM);
    float* gs   = b2s + KDIM;
    float* bts  = gs + KDIM;

    int t = threadIdx.x;
    int e0 = blockIdx.x * TM;

    load_A_transposed(As, efeat, e0, E, t);
    copy_B(Bs1, g_wT[0], t);
    copy_B(Bs2, g_wT[3], t);
    if (t < TM) {
        int e = e0 + t;
        sidx[t] = (e < E) ? srcidx[e] : 0;
        didx[t] = (e < E) ? dstidx[e] : 0;
    } else {
        int c = t - TM;   // 0..127
        b2s[c] = b2[c];
        gs[c]  = gamma[c];
        bts[c] = beta[c];
    }
    __syncthreads();

    int tx = t & 15, ty = t >> 4;
    int row0 = ty * 8, col0 = tx * 8;

    // ---- GEMM1: mlp_efeat tile ----
    u64 acc[32];
#pragma unroll
    for (int i = 0; i < 32; i++) acc[i] = 0ull;
    gemm128(As, Bs1, acc, row0, col0);
    __syncthreads();   // all reads of As done before overwrite

    // ---- epilogue 1: + gathered node projections, SiLU, write transposed into As ----
    const float* srcp = g_proj[0];
    const float* dstp = g_proj[1];
    float y[8][8];
#pragma unroll
    for (int r = 0; r < 8; r++) {
        int is = sidx[row0 + r], id = didx[row0 + r];
        const float* ps = srcp + (size_t)is * KDIM + col0;
        const float* pd = dstp + (size_t)id * KDIM + col0;
        float4 s0 = *(const float4*)ps,       s1 = *(const float4*)(ps + 4);
        float4 d0 = *(const float4*)pd,       d1 = *(const float4*)(pd + 4);
        float g[8] = {s0.x + d0.x, s0.y + d0.y, s0.z + d0.z, s0.w + d0.w,
                      s1.x + d1.x, s1.y + d1.y, s1.z + d1.z, s1.w + d1.w};
#pragma unroll
        for (int c2 = 0; c2 < 4; c2++) {
            float2 f = upk(acc[r * 4 + c2]);
            float x0 = f.x + g[c2 * 2 + 0];
            float x1 = f.y + g[c2 * 2 + 1];
            y[r][c2 * 2 + 0] = x0 * __fdividef(1.f, 1.f + __expf(-x0));
            y[r][c2 * 2 + 1] = x1 * __fdividef(1.f, 1.f + __expf(-x1));
        }
    }
    // s tile transposed: As[k = GEMM1 col][m = edge row]
#pragma unroll
    for (int c = 0; c < 8; c++) {
        *(float4*)(As + (col0 + c) * SA + row0 + 0) = make_float4(y[0][c], y[1][c], y[2][c], y[3][c]);
        *(float4*)(As + (col0 + c) * SA + row0 + 4) = make_float4(y[4][c], y[5][c], y[6][c], y[7][c]);
    }
    __syncthreads();

    // ---- GEMM2: h = silu(sum) @ w2^T ----
#pragma unroll
    for (int i = 0; i < 32; i++) acc[i] = 0ull;
    gemm128(As, Bs2, acc, row0, col0);

    // ---- epilogue 2: +b2, LayerNorm over 128 (16 lanes share a row), store ----
#pragma unroll
    for (int r = 0; r < 8; r++) {
        float h[8];
#pragma unroll
        for (int c2 = 0; c2 < 4; c2++) {
            float2 f = upk(acc[r * 4 + c2]);
            h[c2 * 2 + 0] = f.x + b2s[col0 + c2 * 2 + 0];
            h[c2 * 2 + 1] = f.y + b2s[col0 + c2 * 2 + 1];
        }
        float s = 0.f, ss = 0.f;
#pragma unroll
        for (int c = 0; c < 8; c++) { s += h[c]; ss += h[c] * h[c]; }
#pragma unroll
        for (int m = 8; m >= 1; m >>= 1) {
            s  += __shfl_xor_sync(0xffffffffu, s,  m);
            ss += __shfl_xor_sync(0xffffffffu, ss, m);
        }
        float mu   = s * (1.f / 128.f);
        float var  = ss * (1.f / 128.f) - mu * mu;
        float rstd = rsqrtf(var + 1e-5f);
        int e = e0 + row0 + r;
        if (e < E) {
            float o[8];
#pragma unroll
            for (int c = 0; c < 8; c++)
                o[c] = (h[c] - mu) * rstd * gs[col0 + c] + bts[col0 + c];
            float* po = out + (size_t)e * KDIM + col0;
            *(float4*)(po + 0) = make_float4(o[0], o[1], o[2], o[3]);
            *(float4*)(po + 4) = make_float4(o[4], o[5], o[6], o[7]);
        }
    }
}

// ---------------- launch ----------------
extern "C" void kernel_launch(void* const* d_in, const int* in_sizes, int n_in,
                              void* d_out, int out_size) {
    const float* efeat    = (const float*)d_in[0];
    const float* src_feat = (const float*)d_in[1];
    const float* dst_feat = (const float*)d_in[2];
    const int*   src_idx  = (const int*)  d_in[3];
    const int*   dst_idx  = (const int*)  d_in[4];
    const float* w_efeat  = (const float*)d_in[5];
    const float* w_src    = (const float*)d_in[6];
    const float* w_dst    = (const float*)d_in[7];
    const float* b1       = (const float*)d_in[8];
    const float* w2       = (const float*)d_in[9];
    const float* b2       = (const float*)d_in[10];
    const float* ln_gamma = (const float*)d_in[11];
    const float* ln_beta  = (const float*)d_in[12];
    float* out = (float*)d_out;

    int E = in_sizes[3];           // src_idx element count
    int N = in_sizes[1] / KDIM;    // node count

    const int node_smem = 2 * KDIM * SA * (int)sizeof(float);                       // 135168 B
    const int edge_smem = (3 * KDIM * SA + 2 * TM + 3 * KDIM) * (int)sizeof(float); // 205312 B
    cudaFuncSetAttribute(node_kernel, cudaFuncAttributeMaxDynamicSharedMemorySize, node_smem);
    cudaFuncSetAttribute(edge_kernel, cudaFuncAttributeMaxDynamicSharedMemorySize, edge_smem);

    // 1) weights -> k-major
    wtranspose_kernel<<<4, 256>>>(w_efeat, w_src, w_dst, w2);

    // 2) node projections (bias b1 folded into dst branch, as in reference)
    int node_grid = (N + TM - 1) / TM;
    node_kernel<<<node_grid, NTHREADS, node_smem>>>(src_feat, nullptr, N, 0, 1);
    node_kernel<<<node_grid, NTHREADS, node_smem>>>(dst_feat, b1,      N, 1, 2);

    // 3) fused edge pipeline
    int edge_grid = (E + TM - 1) / TM;
    edge_kernel<<<edge_grid, NTHREADS, edge_smem>>>(efeat, src_idx, dst_idx,
                                                    b2, ln_gamma, ln_beta, out, E);
}

// round 11
// speedup vs baseline: 1.5643x; 1.5643x over previous
#include <cuda_runtime.h>

// ---------------- problem constants ----------------
#define KDIM 128          // feature / hidden / out dim
#define TM   128          // edges (rows) per CTA tile
#define SA   132          // padded smem stride (floats)
#define NTHREADS 256
#define MAX_NODES 100000

// ---------------- device scratch (no cudaMalloc allowed) ----------------
__device__ float g_wT[4][KDIM * KDIM];            // k-major weights: 0=w_efeat,1=w_src,2=w_dst,3=w2
__device__ float g_proj[2][MAX_NODES * KDIM];     // 0 = mlp_src, 1 = mlp_dst(+b1)

typedef unsigned long long u64;

// ---------------- f32x2 packed helpers (Blackwell sm_103a) ----------------
__device__ __forceinline__ u64 dup2(float x) {
    u64 r; asm("mov.b64 %0,{%1,%1};" : "=l"(r) : "f"(x)); return r;
}
__device__ __forceinline__ void fma2(u64 &d, u64 a, u64 b) {
    asm("fma.rn.f32x2 %0,%1,%2,%0;" : "+l"(d) : "l"(a), "l"(b));
}
__device__ __forceinline__ float2 upk(u64 v) {
    float2 f; asm("mov.b64 {%0,%1},%2;" : "=f"(f.x), "=f"(f.y) : "l"(v)); return f;
}

// ---------------- weight pre-transpose: g_wT[b][k*128+n] = w[n*128+k] ----------------
__global__ void wtranspose_kernel(const float* __restrict__ w0, const float* __restrict__ w1,
                                  const float* __restrict__ w2_, const float* __restrict__ w3) {
    const float* src = (blockIdx.x == 0) ? w0 : (blockIdx.x == 1) ? w1 : (blockIdx.x == 2) ? w2_ : w3;
    float* dst = g_wT[blockIdx.x];
    for (int v = threadIdx.x; v < KDIM * KDIM; v += blockDim.x) {
        int k = v & (KDIM - 1);
        int n = v >> 7;
        dst[k * KDIM + n] = src[n * KDIM + k];
    }
}

// ---------------- smem loaders ----------------
// Load a [TM x 128] row-major tile transposed into As[k][m] (stride SA), zero-pad OOB rows.
__device__ __forceinline__ void load_A_transposed(float* As, const float* __restrict__ feat,
                                                  int base, int limit, int t) {
    int lane = t & 31, warp = t >> 5;
    int q  = lane >> 3;   // 0..3  (row offset)
    int kc = lane & 7;    // 0..7  (float4 chunk within 8)
#pragma unroll
    for (int i = 0; i < 16; i++) {
        int m     = q + 4 * warp + 32 * (i & 3);   // 0..127
        int chunk = kc + 8 * (i >> 2);             // 0..31
        int row   = base + m;
        float4 v = make_float4(0.f, 0.f, 0.f, 0.f);
        if (row < limit)
            v = *(const float4*)(feat + (size_t)row * KDIM + chunk * 4);
        int k = chunk * 4;
        As[(k + 0) * SA + m] = v.x;
        As[(k + 1) * SA + m] = v.y;
        As[(k + 2) * SA + m] = v.z;
        As[(k + 3) * SA + m] = v.w;
    }
}

// Copy pre-transposed weights (dense, stride 128) into padded smem (stride SA).
__device__ __forceinline__ void copy_B(float* Bs, const float* __restrict__ wT, int t) {
#pragma unroll
    for (int i = 0; i < 16; i++) {
        int v = t + i * NTHREADS;
        int k = v >> 5;
        int n = (v & 31) * 4;
        *(float4*)(Bs + k * SA + n) = *(const float4*)(wT + k * KDIM + n);
    }
}

// ---------------- core GEMM: acc[m][n] += sum_k As[k][m] * Bs[k][n], 8x8 per thread ----------------
__device__ __forceinline__ void gemm128(const float* As, const float* Bs,
                                        u64 acc[32], int row0, int col0) {
#pragma unroll 2
    for (int k = 0; k < KDIM; k++) {
        const float* ap = As + k * SA + row0;
        float4 a0 = *(const float4*)ap;
        float4 a1 = *(const float4*)(ap + 4);
        const u64* bp = (const u64*)(Bs + k * SA + col0);
        u64 b0 = bp[0], b1 = bp[1], b2 = bp[2], b3 = bp[3];
        float a[8] = {a0.x, a0.y, a0.z, a0.w, a1.x, a1.y, a1.z, a1.w};
#pragma unroll
        for (int r = 0; r < 8; r++) {
            u64 ad = dup2(a[r]);
            fma2(acc[r * 4 + 0], ad, b0);
            fma2(acc[r * 4 + 1], ad, b1);
            fma2(acc[r * 4 + 2], ad, b2);
            fma2(acc[r * 4 + 3], ad, b3);
        }
    }
}

// ---------------- node projection kernel: g_proj[which] = feat @ wT (+bias) ----------------
__global__ void __launch_bounds__(NTHREADS, 1)
node_kernel(const float* __restrict__ feat, const float* __restrict__ bias,
            int N, int which, int wsel) {
    extern __shared__ float sm[];
    float* As = sm;
    float* Bs = sm + KDIM * SA;
    int t = threadIdx.x;
    int n0 = blockIdx.x * TM;

    load_A_transposed(As, feat, n0, N, t);
    copy_B(Bs, g_wT[wsel], t);
    __syncthreads();

    int tx = t & 15, ty = t >> 4;
    int row0 = ty * 8, col0 = tx * 8;

    u64 acc[32];
#pragma unroll
    for (int i = 0; i < 32; i++) acc[i] = 0ull;
    gemm128(As, Bs, acc, row0, col0);

    float bb[8];
#pragma unroll
    for (int c = 0; c < 8; c++) bb[c] = bias ? __ldg(bias + col0 + c) : 0.f;

    float* outp = g_proj[which];
#pragma unroll
    for (int r = 0; r < 8; r++) {
        int m = n0 + row0 + r;
        if (m < N) {
            float o[8];
#pragma unroll
            for (int c2 = 0; c2 < 4; c2++) {
                float2 f = upk(acc[r * 4 + c2]);
                o[c2 * 2 + 0] = f.x + bb[c2 * 2 + 0];
                o[c2 * 2 + 1] = f.y + bb[c2 * 2 + 1];
            }
            float* po = outp + (size_t)m * KDIM + col0;
            *(float4*)(po + 0) = make_float4(o[0], o[1], o[2], o[3]);
            *(float4*)(po + 4) = make_float4(o[4], o[5], o[6], o[7]);
        }
    }
}

// ---------------- fused edge kernel: GEMM1 + gather + SiLU + GEMM2 + LayerNorm ----------------
__global__ void __launch_bounds__(NTHREADS, 1)
edge_kernel(const float* __restrict__ efeat,
            const int* __restrict__ srcidx, const int* __restrict__ dstidx,
            const float* __restrict__ b2, const float* __restrict__ gamma,
            const float* __restrict__ beta,
            float* __restrict__ out, int E) {
    extern __shared__ float sm[];
    float* As  = sm;
    float* Bs1 = sm + 1 * KDIM * SA;
    float* Bs2 = sm + 2 * KDIM * SA;
    float* tail = sm + 3 * KDIM * SA;
    int*   sidx = (int*)tail;
    int*   didx = sidx + TM;
    float* b2s  = (float*)(didx + TM);
    float* gs   = b2s + KDIM;
    float* bts  = gs + KDIM;

    int t = threadIdx.x;
    int e0 = blockIdx.x * TM;

    load_A_transposed(As, efeat, e0, E, t);
    copy_B(Bs1, g_wT[0], t);
    copy_B(Bs2, g_wT[3], t);
    if (t < TM) {
        int e = e0 + t;
        sidx[t] = (e < E) ? srcidx[e] : 0;
        didx[t] = (e < E) ? dstidx[e] : 0;
    } else {
        int c = t - TM;   // 0..127
        b2s[c] = b2[c];
        gs[c]  = gamma[c];
        bts[c] = beta[c];
    }
    __syncthreads();

    int tx = t & 15, ty = t >> 4;
    int row0 = ty * 8, col0 = tx * 8;

    // ---- GEMM1: mlp_efeat tile ----
    u64 acc[32];
#pragma unroll
    for (int i = 0; i < 32; i++) acc[i] = 0ull;
    gemm128(As, Bs1, acc, row0, col0);
    __syncthreads();   // all reads of As done before overwrite

    // ---- epilogue 1: + gathered node projections, SiLU, write transposed into As ----
    const float* srcp = g_proj[0];
    const float* dstp = g_proj[1];
    float y[8][8];
#pragma unroll
    for (int r = 0; r < 8; r++) {
        int is = sidx[row0 + r], id = didx[row0 + r];
        const float* ps = srcp + (size_t)is * KDIM + col0;
        const float* pd = dstp + (size_t)id * KDIM + col0;
        float4 s0 = *(const float4*)ps,       s1 = *(const float4*)(ps + 4);
        float4 d0 = *(const float4*)pd,       d1 = *(const float4*)(pd + 4);
        float g[8] = {s0.x + d0.x, s0.y + d0.y, s0.z + d0.z, s0.w + d0.w,
                      s1.x + d1.x, s1.y + d1.y, s1.z + d1.z, s1.w + d1.w};
#pragma unroll
        for (int c2 = 0; c2 < 4; c2++) {
            float2 f = upk(acc[r * 4 + c2]);
            float x0 = f.x + g[c2 * 2 + 0];
            float x1 = f.y + g[c2 * 2 + 1];
            y[r][c2 * 2 + 0] = x0 * __fdividef(1.f, 1.f + __expf(-x0));
            y[r][c2 * 2 + 1] = x1 * __fdividef(1.f, 1.f + __expf(-x1));
        }
    }
    // s tile transposed: As[k = GEMM1 col][m = edge row]
#pragma unroll
    for (int c = 0; c < 8; c++) {
        *(float4*)(As + (col0 + c) * SA + row0 + 0) = make_float4(y[0][c], y[1][c], y[2][c], y[3][c]);
        *(float4*)(As + (col0 + c) * SA + row0 + 4) = make_float4(y[4][c], y[5][c], y[6][c], y[7][c]);
    }
    __syncthreads();

    // ---- GEMM2: h = silu(sum) @ w2^T ----
#pragma unroll
    for (int i = 0; i < 32; i++) acc[i] = 0ull;
    gemm128(As, Bs2, acc, row0, col0);

    // ---- epilogue 2: +b2, LayerNorm over 128 (16 lanes share a row), store ----
#pragma unroll
    for (int r = 0; r < 8; r++) {
        float h[8];
#pragma unroll
        for (int c2 = 0; c2 < 4; c2++) {
            float2 f = upk(acc[r * 4 + c2]);
            h[c2 * 2 + 0] = f.x + b2s[col0 + c2 * 2 + 0];
            h[c2 * 2 + 1] = f.y + b2s[col0 + c2 * 2 + 1];
        }
        float s = 0.f, ss = 0.f;
#pragma unroll
        for (int c = 0; c < 8; c++) { s += h[c]; ss += h[c] * h[c]; }
#pragma unroll
        for (int m = 8; m >= 1; m >>= 1) {
            s  += __shfl_xor_sync(0xffffffffu, s,  m);
            ss += __shfl_xor_sync(0xffffffffu, ss, m);
        }
        float mu   = s * (1.f / 128.f);
        float var  = ss * (1.f / 128.f) - mu * mu;
        float rstd = rsqrtf(var + 1e-5f);
        int e = e0 + row0 + r;
        if (e < E) {
            float o[8];
#pragma unroll
            for (int c = 0; c < 8; c++)
                o[c] = (h[c] - mu) * rstd * gs[col0 + c] + bts[col0 + c];
            float* po = out + (size_t)e * KDIM + col0;
            *(float4*)(po + 0) = make_float4(o[0], o[1], o[2], o[3]);
            *(float4*)(po + 4) = make_float4(o[4], o[5], o[6], o[7]);
        }
    }
}

// ---------------- launch ----------------
extern "C" void kernel_launch(void* const* d_in, const int* in_sizes, int n_in,
                              void* d_out, int out_size) {
    const float* efeat    = (const float*)d_in[0];
    const float* src_feat = (const float*)d_in[1];
    const float* dst_feat = (const float*)d_in[2];
    const int*   src_idx  = (const int*)  d_in[3];
    const int*   dst_idx  = (const int*)  d_in[4];
    const float* w_efeat  = (const float*)d_in[5];
    const float* w_src    = (const float*)d_in[6];
    const float* w_dst    = (const float*)d_in[7];
    const float* b1       = (const float*)d_in[8];
    const float* w2       = (const float*)d_in[9];
    const float* b2       = (const float*)d_in[10];
    const float* ln_gamma = (const float*)d_in[11];
    const float* ln_beta  = (const float*)d_in[12];
    float* out = (float*)d_out;

    int E = in_sizes[3];           // src_idx element count
    int N = in_sizes[1] / KDIM;    // node count

    const int node_smem = 2 * KDIM * SA * (int)sizeof(float);                       // 135168 B
    const int edge_smem = (3 * KDIM * SA + 2 * TM + 3 * KDIM) * (int)sizeof(float); // 205312 B
    cudaFuncSetAttribute(node_kernel, cudaFuncAttributeMaxDynamicSharedMemorySize, node_smem);
    cudaFuncSetAttribute(edge_kernel, cudaFuncAttributeMaxDynamicSharedMemorySize, edge_smem);

    // 1) weights -> k-major
    wtranspose_kernel<<<4, 256>>>(w_efeat, w_src, w_dst, w2);

    // 2) node projections (bias b1 folded into dst branch, as in reference)
    int node_grid = (N + TM - 1) / TM;
    node_kernel<<<node_grid, NTHREADS, node_smem>>>(src_feat, nullptr, N, 0, 1);
    node_kernel<<<node_grid, NTHREADS, node_smem>>>(dst_feat, b1,      N, 1, 2);

    // 3) fused edge pipeline
    int edge_grid = (E + TM - 1) / TM;
    edge_kernel<<<edge_grid, NTHREADS, edge_smem>>>(efeat, src_idx, dst_idx,
                                                    b2, ln_gamma, ln_beta, out, E);
}

// round 12
// speedup vs baseline: 1.7417x; 1.1134x over previous
#include <cuda_runtime.h>

// ---------------- problem constants ----------------
#define KDIM 128          // feature / hidden / out dim
#define TM   128          // edges (rows) per CTA tile
#define SA   132          // padded smem stride (floats)
#define NTHREADS 256
#define MAX_NODES 100000

// ---------------- device scratch (no cudaMalloc allowed) ----------------
__device__ float g_wT[4][KDIM * KDIM];            // k-major weights: 0=w_efeat,1=w_src,2=w_dst,3=w2
__device__ float g_proj[2][MAX_NODES * KDIM];     // 0 = mlp_src, 1 = mlp_dst(+b1)

typedef unsigned long long u64;
struct __align__(16) U2 { u64 x, y; };

// ---------------- f32x2 packed helpers (Blackwell sm_103a) ----------------
__device__ __forceinline__ u64 dup2(float x) {
    u64 r; asm("mov.b64 %0,{%1,%1};" : "=l"(r) : "f"(x)); return r;
}
__device__ __forceinline__ void fma2(u64 &d, u64 a, u64 b) {
    asm("fma.rn.f32x2 %0,%1,%2,%0;" : "+l"(d) : "l"(a), "l"(b));
}
__device__ __forceinline__ float2 upk(u64 v) {
    float2 f; asm("mov.b64 {%0,%1},%2;" : "=f"(f.x), "=f"(f.y) : "l"(v)); return f;
}

// ---------------- weight pre-transpose: g_wT[b][k*128+n] = w[n*128+k] ----------------
__global__ void wtranspose_kernel(const float* __restrict__ w0, const float* __restrict__ w1,
                                  const float* __restrict__ w2_, const float* __restrict__ w3) {
    const float* src = (blockIdx.x == 0) ? w0 : (blockIdx.x == 1) ? w1 : (blockIdx.x == 2) ? w2_ : w3;
    float* dst = g_wT[blockIdx.x];
    for (int v = threadIdx.x; v < KDIM * KDIM; v += blockDim.x) {
        int k = v & (KDIM - 1);
        int n = v >> 7;
        dst[k * KDIM + n] = src[n * KDIM + k];
    }
}

// ---------------- smem loaders ----------------
// Load a [TM x 128] row-major tile transposed into As[k][m] (stride SA), zero-pad OOB rows.
__device__ __forceinline__ void load_A_transposed(float* As, const float* __restrict__ feat,
                                                  int base, int limit, int t) {
    int lane = t & 31, warp = t >> 5;
    int q  = lane >> 3;   // 0..3  (row offset)
    int kc = lane & 7;    // 0..7  (float4 chunk within 8)
#pragma unroll
    for (int i = 0; i < 16; i++) {
        int m     = q + 4 * warp + 32 * (i & 3);   // 0..127
        int chunk = kc + 8 * (i >> 2);             // 0..31
        int row   = base + m;
        float4 v = make_float4(0.f, 0.f, 0.f, 0.f);
        if (row < limit)
            v = *(const float4*)(feat + (size_t)row * KDIM + chunk * 4);
        int k = chunk * 4;
        As[(k + 0) * SA + m] = v.x;
        As[(k + 1) * SA + m] = v.y;
        As[(k + 2) * SA + m] = v.z;
        As[(k + 3) * SA + m] = v.w;
    }
}

// Copy pre-transposed weights (dense, stride 128) into padded smem (stride SA).
__device__ __forceinline__ void copy_B(float* Bs, const float* __restrict__ wT, int t) {
#pragma unroll
    for (int i = 0; i < 16; i++) {
        int v = t + i * NTHREADS;
        int k = v >> 5;
        int n = (v & 31) * 4;
        *(float4*)(Bs + k * SA + n) = *(const float4*)(wT + k * KDIM + n);
    }
}

// ---------------- core GEMM: acc += A^T B, 8 rows x 8 cols per thread ----------------
// Thread (tx,ty) owns rows [ty*8, ty*8+8) and columns {4tx..4tx+3, 64+4tx..64+4tx+3}.
// B fetch = two LDS.128 at float4 slots tx and tx+16 -> conflict-free across the
// 8-lane crossbar phases (banks 4tx..4tx+3 sweep all 32 banks exactly once).
// acc pair layout: acc[r*4+0]=(c0,c0+1) acc[r*4+1]=(c0+2,c0+3)
//                  acc[r*4+2]=(c1,c1+1) acc[r*4+3]=(c1+2,c1+3)
__device__ __forceinline__ void gemm128(const float* As, const float* Bs,
                                        u64 acc[32], int row0, int tx) {
#pragma unroll 2
    for (int k = 0; k < KDIM; k++) {
        const float* ap = As + k * SA + row0;
        float4 a0 = *(const float4*)ap;
        float4 a1 = *(const float4*)(ap + 4);
        const U2* bp = (const U2*)(Bs + k * SA);
        U2 bA = bp[tx];        // cols 4tx .. 4tx+3
        U2 bB = bp[tx + 16];   // cols 64+4tx .. 64+4tx+3
        float a[8] = {a0.x, a0.y, a0.z, a0.w, a1.x, a1.y, a1.z, a1.w};
#pragma unroll
        for (int r = 0; r < 8; r++) {
            u64 ad = dup2(a[r]);
            fma2(acc[r * 4 + 0], ad, bA.x);
            fma2(acc[r * 4 + 1], ad, bA.y);
            fma2(acc[r * 4 + 2], ad, bB.x);
            fma2(acc[r * 4 + 3], ad, bB.y);
        }
    }
}

// ---------------- node projection kernel: g_proj[which] = feat @ wT (+bias) ----------------
__global__ void __launch_bounds__(NTHREADS, 1)
node_kernel(const float* __restrict__ feat, const float* __restrict__ bias,
            int N, int which, int wsel) {
    extern __shared__ float sm[];
    float* As = sm;
    float* Bs = sm + KDIM * SA;
    int t = threadIdx.x;
    int n0 = blockIdx.x * TM;

    load_A_transposed(As, feat, n0, N, t);
    copy_B(Bs, g_wT[wsel], t);
    __syncthreads();

    int tx = t & 15, ty = t >> 4;
    int row0 = ty * 8;
    int c0 = 4 * tx, c1 = 64 + 4 * tx;

    u64 acc[32];
#pragma unroll
    for (int i = 0; i < 32; i++) acc[i] = 0ull;
    gemm128(As, Bs, acc, row0, tx);

    float bb[8];
    if (bias) {
        float4 t0 = *(const float4*)(bias + c0);
        float4 t1 = *(const float4*)(bias + c1);
        bb[0] = t0.x; bb[1] = t0.y; bb[2] = t0.z; bb[3] = t0.w;
        bb[4] = t1.x; bb[5] = t1.y; bb[6] = t1.z; bb[7] = t1.w;
    } else {
#pragma unroll
        for (int i = 0; i < 8; i++) bb[i] = 0.f;
    }

    float* outp = g_proj[which];
#pragma unroll
    for (int r = 0; r < 8; r++) {
        int m = n0 + row0 + r;
        if (m < N) {
            float o[8];
#pragma unroll
            for (int j = 0; j < 4; j++) {
                float2 f = upk(acc[r * 4 + j]);
                o[j * 2 + 0] = f.x + bb[j * 2 + 0];
                o[j * 2 + 1] = f.y + bb[j * 2 + 1];
            }
            float* po = outp + (size_t)m * KDIM;
            *(float4*)(po + c0) = make_float4(o[0], o[1], o[2], o[3]);
            *(float4*)(po + c1) = make_float4(o[4], o[5], o[6], o[7]);
        }
    }
}

// ---------------- fused edge kernel: GEMM1 + gather + SiLU + GEMM2 + LayerNorm ----------------
__global__ void __launch_bounds__(NTHREADS, 1)
edge_kernel(const float* __restrict__ efeat,
            const int* __restrict__ srcidx, const int* __restrict__ dstidx,
            const float* __restrict__ b2, const float* __restrict__ gamma,
            const float* __restrict__ beta,
            float* __restrict__ out, int E) {
    extern __shared__ float sm[];
    float* As  = sm;
    float* Bs1 = sm + 1 * KDIM * SA;
    float* Bs2 = sm + 2 * KDIM * SA;
    float* tail = sm + 3 * KDIM * SA;
    int*   sidx = (int*)tail;
    int*   didx = sidx + TM;
    float* b2s  = (float*)(didx + TM);
    float* gs   = b2s + KDIM;
    float* bts  = gs + KDIM;

    int t = threadIdx.x;
    int e0 = blockIdx.x * TM;

    load_A_transposed(As, efeat, e0, E, t);
    copy_B(Bs1, g_wT[0], t);
    copy_B(Bs2, g_wT[3], t);
    if (t < TM) {
        int e = e0 + t;
        sidx[t] = (e < E) ? srcidx[e] : 0;
        didx[t] = (e < E) ? dstidx[e] : 0;
    } else {
        int c = t - TM;   // 0..127
        b2s[c] = b2[c];
        gs[c]  = gamma[c];
        bts[c] = beta[c];
    }
    __syncthreads();

    int tx = t & 15, ty = t >> 4;
    int row0 = ty * 8;
    int c0 = 4 * tx, c1 = 64 + 4 * tx;

    // ---- GEMM1: mlp_efeat tile ----
    u64 acc[32];
#pragma unroll
    for (int i = 0; i < 32; i++) acc[i] = 0ull;
    gemm128(As, Bs1, acc, row0, tx);
    __syncthreads();   // all reads of As done before overwrite

    // ---- epilogue 1: + gathered node projections, SiLU, write transposed into As ----
    const float* srcp = g_proj[0];
    const float* dstp = g_proj[1];
    float y[8][8];
#pragma unroll
    for (int r = 0; r < 8; r++) {
        int is = sidx[row0 + r], id = didx[row0 + r];
        const float* ps = srcp + (size_t)is * KDIM;
        const float* pd = dstp + (size_t)id * KDIM;
        float4 s0 = *(const float4*)(ps + c0), s1 = *(const float4*)(ps + c1);
        float4 d0 = *(const float4*)(pd + c0), d1 = *(const float4*)(pd + c1);
        float g[8] = {s0.x + d0.x, s0.y + d0.y, s0.z + d0.z, s0.w + d0.w,
                      s1.x + d1.x, s1.y + d1.y, s1.z + d1.z, s1.w + d1.w};
#pragma unroll
        for (int j = 0; j < 4; j++) {
            float2 f = upk(acc[r * 4 + j]);
            float x0 = f.x + g[j * 2 + 0];
            float x1 = f.y + g[j * 2 + 1];
            y[r][j * 2 + 0] = x0 * __fdividef(1.f, 1.f + __expf(-x0));
            y[r][j * 2 + 1] = x1 * __fdividef(1.f, 1.f + __expf(-x1));
        }
    }
    // silu tile transposed: As[k = GEMM1 col][m = edge row]
#pragma unroll
    for (int i = 0; i < 4; i++) {
        *(float4*)(As + (c0 + i) * SA + row0 + 0) = make_float4(y[0][i], y[1][i], y[2][i], y[3][i]);
        *(float4*)(As + (c0 + i) * SA + row0 + 4) = make_float4(y[4][i], y[5][i], y[6][i], y[7][i]);
        *(float4*)(As + (c1 + i) * SA + row0 + 0) = make_float4(y[0][4 + i], y[1][4 + i], y[2][4 + i], y[3][4 + i]);
        *(float4*)(As + (c1 + i) * SA + row0 + 4) = make_float4(y[4][4 + i], y[5][4 + i], y[6][4 + i], y[7][4 + i]);
    }
    __syncthreads();

    // ---- GEMM2: h = silu(sum) @ w2^T ----
#pragma unroll
    for (int i = 0; i < 32; i++) acc[i] = 0ull;
    gemm128(As, Bs2, acc, row0, tx);

    // ---- epilogue 2: +b2, LayerNorm over 128 (16 lanes share a row), store ----
    float bb[8], gg[8], bt[8];
#pragma unroll
    for (int i = 0; i < 4; i++) {
        bb[i] = b2s[c0 + i]; bb[4 + i] = b2s[c1 + i];
        gg[i] = gs[c0 + i];  gg[4 + i] = gs[c1 + i];
        bt[i] = bts[c0 + i]; bt[4 + i] = bts[c1 + i];
    }
#pragma unroll
    for (int r = 0; r < 8; r++) {
        float h[8];
#pragma unroll
        for (int j = 0; j < 4; j++) {
            float2 f = upk(acc[r * 4 + j]);
            h[j * 2 + 0] = f.x + bb[j * 2 + 0];
            h[j * 2 + 1] = f.y + bb[j * 2 + 1];
        }
        float s = 0.f, ss = 0.f;
#pragma unroll
        for (int c = 0; c < 8; c++) { s += h[c]; ss += h[c] * h[c]; }
#pragma unroll
        for (int m = 8; m >= 1; m >>= 1) {
            s  += __shfl_xor_sync(0xffffffffu, s,  m);
            ss += __shfl_xor_sync(0xffffffffu, ss, m);
        }
        float mu   = s * (1.f / 128.f);
        float var  = ss * (1.f / 128.f) - mu * mu;
        float rstd = rsqrtf(var + 1e-5f);
        int e = e0 + row0 + r;
        if (e < E) {
            float o[8];
#pragma unroll
            for (int c = 0; c < 8; c++)
                o[c] = (h[c] - mu) * rstd * gg[c] + bt[c];
            float* po = out + (size_t)e * KDIM;
            *(float4*)(po + c0) = make_float4(o[0], o[1], o[2], o[3]);
            *(float4*)(po + c1) = make_float4(o[4], o[5], o[6], o[7]);
        }
    }
}

// ---------------- launch ----------------
extern "C" void kernel_launch(void* const* d_in, const int* in_sizes, int n_in,
                              void* d_out, int out_size) {
    const float* efeat    = (const float*)d_in[0];
    const float* src_feat = (const float*)d_in[1];
    const float* dst_feat = (const float*)d_in[2];
    const int*   src_idx  = (const int*)  d_in[3];
    const int*   dst_idx  = (const int*)  d_in[4];
    const float* w_efeat  = (const float*)d_in[5];
    const float* w_src    = (const float*)d_in[6];
    const float* w_dst    = (const float*)d_in[7];
    const float* b1       = (const float*)d_in[8];
    const float* w2       = (const float*)d_in[9];
    const float* b2       = (const float*)d_in[10];
    const float* ln_gamma = (const float*)d_in[11];
    const float* ln_beta  = (const float*)d_in[12];
    float* out = (float*)d_out;

    int E = in_sizes[3];           // src_idx element count
    int N = in_sizes[1] / KDIM;    // node count

    const int node_smem = 2 * KDIM * SA * (int)sizeof(float);                       // 135168 B
    const int edge_smem = (3 * KDIM * SA + 2 * TM + 3 * KDIM) * (int)sizeof(float); // 205312 B
    cudaFuncSetAttribute(node_kernel, cudaFuncAttributeMaxDynamicSharedMemorySize, node_smem);
    cudaFuncSetAttribute(edge_kernel, cudaFuncAttributeMaxDynamicSharedMemorySize, edge_smem);

    // 1) weights -> k-major
    wtranspose_kernel<<<4, 256>>>(w_efeat, w_src, w_dst, w2);

    // 2) node projections (bias b1 folded into dst branch, as in reference)
    int node_grid = (N + TM - 1) / TM;
    node_kernel<<<node_grid, NTHREADS, node_smem>>>(src_feat, nullptr, N, 0, 1);
    node_kernel<<<node_grid, NTHREADS, node_smem>>>(dst_feat, b1,      N, 1, 2);

    // 3) fused edge pipeline
    int edge_grid = (E + TM - 1) / TM;
    edge_kernel<<<edge_grid, NTHREADS, edge_smem>>>(efeat, src_idx, dst_idx,
                                                    b2, ln_gamma, ln_beta, out, E);
}

// round 15
// speedup vs baseline: 2.4646x; 1.4150x over previous
#include <cuda_runtime.h>
#include <cuda_bf16.h>
#include <stdint.h>

// ---------------- problem constants ----------------
#define KDIM 128
#define TM   128
#define SA   132            // node-path padded float stride
#define NT_NODE 256
#define NT_EDGE 256
#define MAX_NODES 100000
#define WSTRIDE 136         // bf16 elements per row (272 B) for mma operand tiles
#define WBYTES  (128 * WSTRIDE * 2)   // 34816 B per operand image

// single dynamic smem symbol shared by all kernels
extern __shared__ char dyn_smem[];

// ---------------- device scratch ----------------
__device__ float g_wT[4][KDIM * KDIM];            // k-major fp32 weights (node path)
__device__ float g_proj[2][MAX_NODES * KDIM];     // 0 = mlp_src, 1 = mlp_dst(+b1)
// padded [n][136] bf16 images: 0=w_efeat_hi 1=w_efeat_lo 2=w2_hi 3=w2_lo
__device__ __align__(16) __nv_bfloat16 g_wbf[4][128 * WSTRIDE];

typedef unsigned long long u64;
struct __align__(16) U2 { u64 x, y; };

// ---------------- f32x2 packed helpers (node path) ----------------
__device__ __forceinline__ u64 dup2(float x) {
    u64 r; asm("mov.b64 %0,{%1,%1};" : "=l"(r) : "f"(x)); return r;
}
__device__ __forceinline__ void fma2(u64 &d, u64 a, u64 b) {
    asm("fma.rn.f32x2 %0,%1,%2,%0;" : "+l"(d) : "l"(a), "l"(b));
}
__device__ __forceinline__ float2 upk(u64 v) {
    float2 f; asm("mov.b64 {%0,%1},%2;" : "=f"(f.x), "=f"(f.y) : "l"(v)); return f;
}

// ---------------- mma helpers (portable PTX: ldmatrix + HMMA) ----------------
__device__ __forceinline__ uint32_t smem_to_u32(const void* p) {
    uint32_t a;
    asm("{ .reg .u64 t; cvta.to.shared.u64 t, %1; cvt.u32.u64 %0, t; }" : "=r"(a) : "l"(p));
    return a;
}
__device__ __forceinline__ void ldsm_x4(uint32_t* r, uint32_t addr) {
    asm volatile("ldmatrix.sync.aligned.m8n8.x4.shared.b16 {%0,%1,%2,%3}, [%4];"
                 : "=r"(r[0]), "=r"(r[1]), "=r"(r[2]), "=r"(r[3]) : "r"(addr));
}
__device__ __forceinline__ void mma_bf16(float* d, const uint32_t* a, const uint32_t* b) {
    asm volatile("mma.sync.aligned.m16n8k16.row.col.f32.bf16.bf16.f32 "
                 "{%0,%1,%2,%3}, {%4,%5,%6,%7}, {%8,%9}, {%0,%1,%2,%3};"
                 : "+f"(d[0]), "+f"(d[1]), "+f"(d[2]), "+f"(d[3])
                 : "r"(a[0]), "r"(a[1]), "r"(a[2]), "r"(a[3]), "r"(b[0]), "r"(b[1]));
}
__device__ __forceinline__ uint32_t pack_bf2(__nv_bfloat16 a, __nv_bfloat16 b) {
    return (uint32_t)__bfloat16_as_ushort(a) | ((uint32_t)__bfloat16_as_ushort(b) << 16);
}

// ---------------- weight prep kernels ----------------
__global__ void wtranspose_kernel(const float* __restrict__ w1, const float* __restrict__ w2_) {
    const float* src = (blockIdx.x == 0) ? w1 : w2_;
    float* dst = g_wT[blockIdx.x + 1];   // slots 1 (w_src), 2 (w_dst)
    for (int v = threadIdx.x; v < KDIM * KDIM; v += blockDim.x) {
        int k = v & (KDIM - 1);
        int n = v >> 7;
        dst[k * KDIM + n] = src[n * KDIM + k];
    }
}

// split w ([n][k] row-major) into bf16 hi/lo, padded stride WSTRIDE
__global__ void wprep_bf16(const float* __restrict__ wef, const float* __restrict__ w2) {
    const float* w = blockIdx.x ? w2 : wef;
    __nv_bfloat16* hi = g_wbf[blockIdx.x * 2 + 0];
    __nv_bfloat16* lo = g_wbf[blockIdx.x * 2 + 1];
    for (int v = threadIdx.x; v < 128 * WSTRIDE; v += blockDim.x) {
        int n = v / WSTRIDE, k = v % WSTRIDE;
        float x = (k < 128) ? w[n * 128 + k] : 0.f;
        __nv_bfloat16 h = __float2bfloat16(x);
        __nv_bfloat16 l = __float2bfloat16(x - __bfloat162float(h));
        hi[v] = h; lo[v] = l;
    }
}

// ---------------- node path (fp32 FFMA2, proven) ----------------
__device__ __forceinline__ void load_A_transposed(float* As, const float* __restrict__ feat,
                                                  int base, int limit, int t) {
    int lane = t & 31, warp = t >> 5;
    int q  = lane >> 3;
    int kc = lane & 7;
#pragma unroll
    for (int i = 0; i < 16; i++) {
        int m     = q + 4 * warp + 32 * (i & 3);
        int chunk = kc + 8 * (i >> 2);
        int row   = base + m;
        float4 v = make_float4(0.f, 0.f, 0.f, 0.f);
        if (row < limit)
            v = *(const float4*)(feat + (size_t)row * KDIM + chunk * 4);
        int k = chunk * 4;
        As[(k + 0) * SA + m] = v.x;
        As[(k + 1) * SA + m] = v.y;
        As[(k + 2) * SA + m] = v.z;
        As[(k + 3) * SA + m] = v.w;
    }
}

__device__ __forceinline__ void copy_B(float* Bs, const float* __restrict__ wT, int t) {
#pragma unroll
    for (int i = 0; i < 16; i++) {
        int v = t + i * NT_NODE;
        int k = v >> 5;
        int n = (v & 31) * 4;
        *(float4*)(Bs + k * SA + n) = *(const float4*)(wT + k * KDIM + n);
    }
}

__device__ __forceinline__ void gemm128(const float* As, const float* Bs,
                                        u64 acc[32], int row0, int tx) {
#pragma unroll 2
    for (int k = 0; k < KDIM; k++) {
        const float* ap = As + k * SA + row0;
        float4 a0 = *(const float4*)ap;
        float4 a1 = *(const float4*)(ap + 4);
        const U2* bp = (const U2*)(Bs + k * SA);
        U2 bA = bp[tx];
        U2 bB = bp[tx + 16];
        float a[8] = {a0.x, a0.y, a0.z, a0.w, a1.x, a1.y, a1.z, a1.w};
#pragma unroll
        for (int r = 0; r < 8; r++) {
            u64 ad = dup2(a[r]);
            fma2(acc[r * 4 + 0], ad, bA.x);
            fma2(acc[r * 4 + 1], ad, bA.y);
            fma2(acc[r * 4 + 2], ad, bB.x);
            fma2(acc[r * 4 + 3], ad, bB.y);
        }
    }
}

__global__ void __launch_bounds__(NT_NODE, 1)
node_kernel(const float* __restrict__ feat, const float* __restrict__ bias,
            int N, int which, int wsel) {
    float* sm = (float*)dyn_smem;
    float* As = sm;
    float* Bs = sm + KDIM * SA;
    int t = threadIdx.x;
    int n0 = blockIdx.x * TM;

    load_A_transposed(As, feat, n0, N, t);
    copy_B(Bs, g_wT[wsel], t);
    __syncthreads();

    int tx = t & 15, ty = t >> 4;
    int row0 = ty * 8;
    int c0 = 4 * tx, c1 = 64 + 4 * tx;

    u64 acc[32];
#pragma unroll
    for (int i = 0; i < 32; i++) acc[i] = 0ull;
    gemm128(As, Bs, acc, row0, tx);

    float bb[8];
    if (bias) {
        float4 t0 = *(const float4*)(bias + c0);
        float4 t1 = *(const float4*)(bias + c1);
        bb[0] = t0.x; bb[1] = t0.y; bb[2] = t0.z; bb[3] = t0.w;
        bb[4] = t1.x; bb[5] = t1.y; bb[6] = t1.z; bb[7] = t1.w;
    } else {
#pragma unroll
        for (int i = 0; i < 8; i++) bb[i] = 0.f;
    }

    float* outp = g_proj[which];
#pragma unroll
    for (int r = 0; r < 8; r++) {
        int m = n0 + row0 + r;
        if (m < N) {
            float o[8];
#pragma unroll
            for (int j = 0; j < 4; j++) {
                float2 f = upk(acc[r * 4 + j]);
                o[j * 2 + 0] = f.x + bb[j * 2 + 0];
                o[j * 2 + 1] = f.y + bb[j * 2 + 1];
            }
            float* po = outp + (size_t)m * KDIM;
            *(float4*)(po + c0) = make_float4(o[0], o[1], o[2], o[3]);
            *(float4*)(po + c1) = make_float4(o[4], o[5], o[6], o[7]);
        }
    }
}

// ---------------- fused edge kernel: HMMA bf16x3 GEMM1 + gather/SiLU + GEMM2 + LN ----------------
// smem byte layout
#define SM_SIDX 0
#define SM_DIDX 512
#define SM_B2   1024
#define SM_G    1536
#define SM_BT   2048
#define SM_AHI  4096
#define SM_ALO  (SM_AHI + WBYTES)
#define SM_B1HI (SM_ALO + WBYTES)
#define SM_B1LO (SM_B1HI + WBYTES)
#define SM_B2HI (SM_B1LO + WBYTES)
#define SM_B2LO (SM_B2HI + WBYTES)
#define SM_EDGE_TOTAL (SM_B2LO + WBYTES)   // 4096 + 6*34816 = 212992 B

// shared-fragment bf16x3 GEMM: warp owns 32 rows x 64 cols; hi/lo frags loaded once per k.
__device__ __forceinline__ void gemm_mma(uint32_t aHi, uint32_t bHi, float acc[2][8][4]) {
#pragma unroll
    for (int k = 0; k < 8; k++) {
        uint32_t af[2][2][4];
        uint32_t bf[2][8][2];
#pragma unroll
        for (int mb = 0; mb < 2; mb++) {
            ldsm_x4(af[0][mb], aHi +          mb * (16 * 272) + k * 32);
            ldsm_x4(af[1][mb], aHi + WBYTES + mb * (16 * 272) + k * 32);
        }
#pragma unroll
        for (int p = 0; p < 4; p++) {
            ldsm_x4(&bf[0][2 * p][0], bHi +          p * (16 * 272) + k * 32);
            ldsm_x4(&bf[1][2 * p][0], bHi + WBYTES + p * (16 * 272) + k * 32);
        }
#pragma unroll
        for (int mb = 0; mb < 2; mb++)
#pragma unroll
            for (int nb = 0; nb < 8; nb++) {
                mma_bf16(acc[mb][nb], af[0][mb], bf[0][nb]);  // hi*hi
                mma_bf16(acc[mb][nb], af[0][mb], bf[1][nb]);  // hi*lo
                mma_bf16(acc[mb][nb], af[1][mb], bf[0][nb]);  // lo*hi
            }
    }
}

__global__ void __launch_bounds__(NT_EDGE, 1)
edge_kernel(const float* __restrict__ efeat,
            const int* __restrict__ srcidx, const int* __restrict__ dstidx,
            const float* __restrict__ b2, const float* __restrict__ gamma,
            const float* __restrict__ beta,
            float* __restrict__ out, int E) {
    char* sm = dyn_smem;
    uint32_t sb = smem_to_u32(sm);
    int t = threadIdx.x, w = t >> 5, l = t & 31;
    int e0 = blockIdx.x * TM;

    int* sidx = (int*)(sm + SM_SIDX);
    int* didx = (int*)(sm + SM_DIDX);

    // ---- init: indices + vectors ----
    if (t < TM) {
        int e = e0 + t;
        sidx[t] = (e < E) ? srcidx[e] : 0;
        didx[t] = (e < E) ? dstidx[e] : 0;
    } else {
        int c = t - TM;   // 0..127
        ((float*)(sm + SM_B2))[c] = b2[c];
        ((float*)(sm + SM_G ))[c] = gamma[c];
        ((float*)(sm + SM_BT))[c] = beta[c];
    }
    // ---- copy 4 padded weight images (contiguous 139264 B) into smem ----
    {
        const float4* wsrc = (const float4*)g_wbf;
        float4* wdst = (float4*)(sm + SM_B1HI);
#pragma unroll
        for (int i = 0; i < 34; i++) {
            int v = i * NT_EDGE + t;
            if (v < 4 * (WBYTES / 16)) wdst[v] = wsrc[v];
        }
    }
    // ---- load efeat tile, split hi/lo, store [m][k] stride 272B ----
    {
        const float* ebase = efeat + (size_t)e0 * KDIM;
        char* ahi = sm + SM_AHI;
        char* alo = sm + SM_ALO;
#pragma unroll
        for (int i = 0; i < 16; i++) {
            int idx = i * NT_EDGE + t;
            int row = idx >> 5, c4 = idx & 31;
            float4 v = make_float4(0.f, 0.f, 0.f, 0.f);
            if (e0 + row < E) v = *(const float4*)(ebase + (size_t)row * KDIM + c4 * 4);
            __nv_bfloat16 h0 = __float2bfloat16(v.x), h1 = __float2bfloat16(v.y);
            __nv_bfloat16 h2 = __float2bfloat16(v.z), h3 = __float2bfloat16(v.w);
            __nv_bfloat16 l0 = __float2bfloat16(v.x - __bfloat162float(h0));
            __nv_bfloat16 l1 = __float2bfloat16(v.y - __bfloat162float(h1));
            __nv_bfloat16 l2 = __float2bfloat16(v.z - __bfloat162float(h2));
            __nv_bfloat16 l3 = __float2bfloat16(v.w - __bfloat162float(h3));
            uint32_t off = (uint32_t)row * 272 + c4 * 8;
            *(uint32_t*)(ahi + off)     = pack_bf2(h0, h1);
            *(uint32_t*)(ahi + off + 4) = pack_bf2(h2, h3);
            *(uint32_t*)(alo + off)     = pack_bf2(l0, l1);
            *(uint32_t*)(alo + off + 4) = pack_bf2(l2, l3);
        }
    }
    __syncthreads();

    // warp grid: 4 m-positions x 2 n-positions
    int mq = w & 3, nq = w >> 2;
    // per-lane ldmatrix base offsets
    uint32_t aoff = (uint32_t)((mq * 32 + (l & 15)) * 272 + (l >> 4) * 16);
    uint32_t boff = (uint32_t)((nq * 64 + ((l >> 4) & 1) * 8 + (l & 7)) * 272 + ((l >> 3) & 1) * 16);

    float acc[2][8][4];
#pragma unroll
    for (int i = 0; i < 2; i++)
#pragma unroll
        for (int j = 0; j < 8; j++)
#pragma unroll
            for (int q = 0; q < 4; q++) acc[i][j][q] = 0.f;

    // ---- GEMM1: efeat @ w_efeat^T (bf16x3) ----
    gemm_mma(sb + SM_AHI + aoff, sb + SM_B1HI + boff, acc);
    __syncthreads();   // all A reads complete before overwrite

    // ---- epilogue 1: gather node projections, SiLU, re-split into A buffers ----
    {
        char* ahi = sm + SM_AHI;
        char* alo = sm + SM_ALO;
        int cbase = nq * 64 + 2 * (l & 3);
        const float* p0 = g_proj[0];
        const float* p1 = g_proj[1];
#pragma unroll
        for (int mb = 0; mb < 2; mb++) {
#pragma unroll
            for (int h = 0; h < 2; h++) {
                int rr = mq * 32 + mb * 16 + (l >> 2) + h * 8;
                const float* ps = p0 + (size_t)sidx[rr] * KDIM;
                const float* pd = p1 + (size_t)didx[rr] * KDIM;
#pragma unroll
                for (int nb = 0; nb < 8; nb++) {
                    int c = cbase + nb * 8;
                    float2 s = *(const float2*)(ps + c);
                    float2 dd = *(const float2*)(pd + c);
                    float x0 = acc[mb][nb][2 * h + 0] + s.x + dd.x;
                    float x1 = acc[mb][nb][2 * h + 1] + s.y + dd.y;
                    float y0 = x0 * __fdividef(1.f, 1.f + __expf(-x0));
                    float y1 = x1 * __fdividef(1.f, 1.f + __expf(-x1));
                    __nv_bfloat16 h0 = __float2bfloat16(y0), h1 = __float2bfloat16(y1);
                    __nv_bfloat16 l0 = __float2bfloat16(y0 - __bfloat162float(h0));
                    __nv_bfloat16 l1 = __float2bfloat16(y1 - __bfloat162float(h1));
                    uint32_t off = (uint32_t)rr * 272 + c * 2;
                    *(uint32_t*)(ahi + off) = pack_bf2(h0, h1);
                    *(uint32_t*)(alo + off) = pack_bf2(l0, l1);
                }
            }
        }
    }
    __syncthreads();

    // ---- GEMM2: silu @ w2^T (bf16x3) ----
#pragma unroll
    for (int i = 0; i < 2; i++)
#pragma unroll
        for (int j = 0; j < 8; j++)
#pragma unroll
            for (int q = 0; q < 4; q++) acc[i][j][q] = 0.f;
    gemm_mma(sb + SM_AHI + aoff, sb + SM_B2HI + boff, acc);

    // ---- epilogue 2: +b2, LayerNorm (quad shuffle reduce), store ----
    {
        const float* b2s = (const float*)(sm + SM_B2);
        const float* gs  = (const float*)(sm + SM_G);
        const float* bts = (const float*)(sm + SM_BT);
        int cbase = nq * 64 + 2 * (l & 3);
#pragma unroll
        for (int mb = 0; mb < 2; mb++) {
#pragma unroll
            for (int h = 0; h < 2; h++) {
                int rr = mq * 32 + mb * 16 + (l >> 2) + h * 8;
                int e = e0 + rr;
                float v[16];
                float sum = 0.f, ssq = 0.f;
#pragma unroll
                for (int nb = 0; nb < 8; nb++) {
                    int c = cbase + nb * 8;
                    float x0 = acc[mb][nb][2 * h + 0] + b2s[c];
                    float x1 = acc[mb][nb][2 * h + 1] + b2s[c + 1];
                    v[nb * 2 + 0] = x0; v[nb * 2 + 1] = x1;
                    sum += x0 + x1;
                    ssq += x0 * x0 + x1 * x1;
                }
                // reduce across the 4 lanes of the quad (xor 1,2 stay within quad)
                sum += __shfl_xor_sync(0xffffffffu, sum, 1);
                ssq += __shfl_xor_sync(0xffffffffu, ssq, 1);
                sum += __shfl_xor_sync(0xffffffffu, sum, 2);
                ssq += __shfl_xor_sync(0xffffffffu, ssq, 2);
                // reduce across the two n-position warps via partial sums in... NOTE:
                // each warp holds only 64 of 128 cols; combine with the partner warp
                // through shared memory.
                __shared__ float red[2][128][2];   // [half][row][sum/ssq]
                if ((l & 3) == 0) {
                    red[nq][rr][0] = sum;
                    red[nq][rr][1] = ssq;
                }
                __syncthreads();
                float tsum = red[0][rr][0] + red[1][rr][0];
                float tssq = red[0][rr][1] + red[1][rr][1];
                __syncthreads();
                float mu   = tsum * (1.f / 128.f);
                float var  = tssq * (1.f / 128.f) - mu * mu;
                float rstd = rsqrtf(var + 1e-5f);
                if (e < E) {
                    float* po = out + (size_t)e * KDIM;
#pragma unroll
                    for (int nb = 0; nb < 8; nb++) {
                        int c = cbase + nb * 8;
                        float2 o;
                        o.x = (v[nb * 2 + 0] - mu) * rstd * gs[c]     + bts[c];
                        o.y = (v[nb * 2 + 1] - mu) * rstd * gs[c + 1] + bts[c + 1];
                        *(float2*)(po + c) = o;
                    }
                }
            }
        }
    }
}

// ---------------- launch ----------------
extern "C" void kernel_launch(void* const* d_in, const int* in_sizes, int n_in,
                              void* d_out, int out_size) {
    const float* efeat    = (const float*)d_in[0];
    const float* src_feat = (const float*)d_in[1];
    const float* dst_feat = (const float*)d_in[2];
    const int*   src_idx  = (const int*)  d_in[3];
    const int*   dst_idx  = (const int*)  d_in[4];
    const float* w_efeat  = (const float*)d_in[5];
    const float* w_src    = (const float*)d_in[6];
    const float* w_dst    = (const float*)d_in[7];
    const float* b1       = (const float*)d_in[8];
    const float* w2       = (const float*)d_in[9];
    const float* b2       = (const float*)d_in[10];
    const float* ln_gamma = (const float*)d_in[11];
    const float* ln_beta  = (const float*)d_in[12];
    float* out = (float*)d_out;

    int E = in_sizes[3];
    int N = in_sizes[1] / KDIM;

    const int node_smem = 2 * KDIM * SA * (int)sizeof(float);
    cudaFuncSetAttribute(node_kernel, cudaFuncAttributeMaxDynamicSharedMemorySize, node_smem);
    cudaFuncSetAttribute(edge_kernel, cudaFuncAttributeMaxDynamicSharedMemorySize, SM_EDGE_TOTAL);

    // 1) weight prep
    wtranspose_kernel<<<2, 256>>>(w_src, w_dst);
    wprep_bf16<<<2, 256>>>(w_efeat, w2);

    // 2) node projections (b1 folded into dst branch)
    int node_grid = (N + TM - 1) / TM;
    node_kernel<<<node_grid, NT_NODE, node_smem>>>(src_feat, nullptr, N, 0, 1);
    node_kernel<<<node_grid, NT_NODE, node_smem>>>(dst_feat, b1,      N, 1, 2);

    // 3) fused edge pipeline (HMMA bf16x3)
    int edge_grid = (E + TM - 1) / TM;
    edge_kernel<<<edge_grid, NT_EDGE, SM_EDGE_TOTAL>>>(efeat, src_idx, dst_idx,
                                                       b2, ln_gamma, ln_beta, out, E);
}

// round 16
// speedup vs baseline: 3.2753x; 1.3289x over previous
#include <cuda_runtime.h>
#include <cuda_fp16.h>
#include <stdint.h>

// ---------------- problem constants ----------------
#define KDIM 128
#define TM   128
#define NT   256
#define MAX_NODES 100000
#define WSTRIDE 136                      // fp16 elements per row (272 B)
#define WBYTES  (128 * WSTRIDE * 2)      // 34816 B per operand image

extern __shared__ char dyn_smem[];

// ---------------- device scratch ----------------
__device__ float g_proj[2][MAX_NODES * KDIM];   // 0 = mlp_src, 1 = mlp_dst(+b1)
// fp16 padded [n][136] weight images: 0=w_efeat 1=w2 (contiguous for edge), 2=w_src 3=w_dst
__device__ __align__(16) __half g_wh[4][128 * WSTRIDE];

// ---------------- mma helpers (portable PTX: ldmatrix + HMMA fp16) ----------------
__device__ __forceinline__ uint32_t smem_to_u32(const void* p) {
    uint32_t a;
    asm("{ .reg .u64 t; cvta.to.shared.u64 t, %1; cvt.u32.u64 %0, t; }" : "=r"(a) : "l"(p));
    return a;
}
__device__ __forceinline__ void ldsm_x4(uint32_t* r, uint32_t addr) {
    asm volatile("ldmatrix.sync.aligned.m8n8.x4.shared.b16 {%0,%1,%2,%3}, [%4];"
                 : "=r"(r[0]), "=r"(r[1]), "=r"(r[2]), "=r"(r[3]) : "r"(addr));
}
__device__ __forceinline__ void mma_f16(float* d, const uint32_t* a, const uint32_t* b) {
    asm volatile("mma.sync.aligned.m16n8k16.row.col.f32.f16.f16.f32 "
                 "{%0,%1,%2,%3}, {%4,%5,%6,%7}, {%8,%9}, {%0,%1,%2,%3};"
                 : "+f"(d[0]), "+f"(d[1]), "+f"(d[2]), "+f"(d[3])
                 : "r"(a[0]), "r"(a[1]), "r"(a[2]), "r"(a[3]), "r"(b[0]), "r"(b[1]));
}
__device__ __forceinline__ uint32_t pack_h2(__half a, __half b) {
    return (uint32_t)__half_as_ushort(a) | ((uint32_t)__half_as_ushort(b) << 16);
}
// split x0,x1 into fp16 hi pair + fp16 lo pair
__device__ __forceinline__ void split2(float x0, float x1, uint32_t &hi, uint32_t &lo) {
    __half h0 = __float2half_rn(x0), h1 = __float2half_rn(x1);
    __half l0 = __float2half_rn(x0 - __half2float(h0));
    __half l1 = __float2half_rn(x1 - __half2float(h1));
    hi = pack_h2(h0, h1);
    lo = pack_h2(l0, l1);
}

// ---------------- weight prep: fp16 padded images ----------------
__global__ void wprep(const float* __restrict__ wef, const float* __restrict__ w2,
                      const float* __restrict__ wsrc, const float* __restrict__ wdst) {
    const float* w = (blockIdx.x == 0) ? wef : (blockIdx.x == 1) ? w2
                   : (blockIdx.x == 2) ? wsrc : wdst;
    __half* hi = g_wh[blockIdx.x];
    for (int v = threadIdx.x; v < 128 * WSTRIDE; v += blockDim.x) {
        int n = v / WSTRIDE, k = v % WSTRIDE;
        float x = (k < 128) ? w[n * 128 + k] : 0.f;
        hi[v] = __float2half_rn(x);
    }
}

// ---------------- shared-fragment fp16x2 GEMM core ----------------
// warp owns 32 rows x 64 cols of a 128x128 tile; A hi/lo at aHi/aHi+WBYTES; B fp16 at bHi.
// 2 passes: ah*bh + al*bh. 8 ldsm + 32 HMMA per k-step.
__device__ __forceinline__ void gemm_mma2(uint32_t aHi, uint32_t bHi, float acc[2][8][4]) {
#pragma unroll
    for (int k = 0; k < 8; k++) {
        uint32_t af[2][2][4];   // [hi/lo][mb][frag]
        uint32_t bf[8][2];
#pragma unroll
        for (int mb = 0; mb < 2; mb++) {
            ldsm_x4(af[0][mb], aHi +          mb * (16 * 272) + k * 32);
            ldsm_x4(af[1][mb], aHi + WBYTES + mb * (16 * 272) + k * 32);
        }
#pragma unroll
        for (int p = 0; p < 4; p++)
            ldsm_x4(&bf[2 * p][0], bHi + p * (16 * 272) + k * 32);
#pragma unroll
        for (int mb = 0; mb < 2; mb++)
#pragma unroll
            for (int nb = 0; nb < 8; nb++) {
                mma_f16(acc[mb][nb], af[0][mb], bf[nb]);   // hi * w
                mma_f16(acc[mb][nb], af[1][mb], bf[nb]);   // lo * w
            }
    }
}

// load a [128 x 128] fp32 row tile, split fp16 hi/lo into padded smem images
__device__ __forceinline__ void load_split_tile(char* ahi, char* alo,
                                                const float* __restrict__ feat,
                                                int base, int limit, int t) {
#pragma unroll
    for (int i = 0; i < 16; i++) {
        int idx = i * NT + t;
        int row = idx >> 5, c4 = idx & 31;
        float4 v = make_float4(0.f, 0.f, 0.f, 0.f);
        if (base + row < limit)
            v = *(const float4*)(feat + (size_t)(base + row) * KDIM + c4 * 4);
        uint32_t h0, l0, h1, l1;
        split2(v.x, v.y, h0, l0);
        split2(v.z, v.w, h1, l1);
        uint32_t off = (uint32_t)row * 272 + c4 * 8;
        *(uint32_t*)(ahi + off)     = h0;
        *(uint32_t*)(ahi + off + 4) = h1;
        *(uint32_t*)(alo + off)     = l0;
        *(uint32_t*)(alo + off + 4) = l1;
    }
}

// ---------------- node projection kernel (HMMA fp16x2) ----------------
// smem: [0,W) A hi | [W,2W) A lo | [2W,3W) B | total 104448 B  -> 2 CTA/SM
#define NSM_TOTAL (3 * WBYTES)

__global__ void __launch_bounds__(NT)
node_kernel(const float* __restrict__ feat, const float* __restrict__ bias,
            int N, int which, int wsel) {
    char* sm = dyn_smem;
    uint32_t sb = smem_to_u32(sm);
    int t = threadIdx.x, w = t >> 5, l = t & 31;
    int n0 = blockIdx.x * TM;

    // weights -> smem
    {
        const float4* wsrc4 = (const float4*)g_wh[wsel];
        float4* wdst = (float4*)(sm + 2 * WBYTES);
#pragma unroll
        for (int i = 0; i < 9; i++) {
            int v = i * NT + t;
            if (v < WBYTES / 16) wdst[v] = wsrc4[v];
        }
    }
    load_split_tile(sm, sm + WBYTES, feat, n0, N, t);
    __syncthreads();

    int mq = w & 3, nq = w >> 2;
    uint32_t aoff = (uint32_t)((mq * 32 + (l & 15)) * 272 + (l >> 4) * 16);
    uint32_t boff = (uint32_t)((nq * 64 + ((l >> 4) & 1) * 8 + (l & 7)) * 272 + ((l >> 3) & 1) * 16);

    float acc[2][8][4];
#pragma unroll
    for (int i = 0; i < 2; i++)
#pragma unroll
        for (int j = 0; j < 8; j++)
#pragma unroll
            for (int q = 0; q < 4; q++) acc[i][j][q] = 0.f;

    gemm_mma2(sb + aoff, sb + 2 * WBYTES + boff, acc);

    // epilogue: +bias (dst branch), fp32 store to g_proj
    float* outp = g_proj[which];
    int cbase = nq * 64 + 2 * (l & 3);
#pragma unroll
    for (int mb = 0; mb < 2; mb++) {
#pragma unroll
        for (int h = 0; h < 2; h++) {
            int rr = mq * 32 + mb * 16 + (l >> 2) + h * 8;
            int m = n0 + rr;
            if (m < N) {
                float* po = outp + (size_t)m * KDIM;
#pragma unroll
                for (int nb = 0; nb < 8; nb++) {
                    int c = cbase + nb * 8;
                    float b0 = bias ? __ldg(bias + c)     : 0.f;
                    float b1v = bias ? __ldg(bias + c + 1) : 0.f;
                    float2 o;
                    o.x = acc[mb][nb][2 * h + 0] + b0;
                    o.y = acc[mb][nb][2 * h + 1] + b1v;
                    *(float2*)(po + c) = o;
                }
            }
        }
    }
}

// ---------------- fused edge kernel: HMMA fp16x2 GEMM1 + gather/SiLU + GEMM2 + LN ----------------
// smem byte layout
#define SM_SIDX 0
#define SM_DIDX 512
#define SM_B2   1024
#define SM_G    1536
#define SM_BT   2048
#define SM_AHI  4096
#define SM_ALO  (SM_AHI + WBYTES)
#define SM_B1H  (SM_ALO + WBYTES)
#define SM_B2H  (SM_B1H + WBYTES)
#define SM_EDGE_TOTAL (SM_B2H + WBYTES)   // 4096 + 4*34816 = 143360 B

__global__ void __launch_bounds__(NT)
edge_kernel(const float* __restrict__ efeat,
            const int* __restrict__ srcidx, const int* __restrict__ dstidx,
            const float* __restrict__ b2, const float* __restrict__ gamma,
            const float* __restrict__ beta,
            float* __restrict__ out, int E) {
    char* sm = dyn_smem;
    uint32_t sb = smem_to_u32(sm);
    int t = threadIdx.x, w = t >> 5, l = t & 31;
    int e0 = blockIdx.x * TM;

    int* sidx = (int*)(sm + SM_SIDX);
    int* didx = (int*)(sm + SM_DIDX);

    if (t < TM) {
        int e = e0 + t;
        sidx[t] = (e < E) ? srcidx[e] : 0;
        didx[t] = (e < E) ? dstidx[e] : 0;
    } else {
        int c = t - TM;
        ((float*)(sm + SM_B2))[c] = b2[c];
        ((float*)(sm + SM_G ))[c] = gamma[c];
        ((float*)(sm + SM_BT))[c] = beta[c];
    }
    // weights (2 contiguous images: w_efeat, w2) -> smem
    {
        const float4* wsrc4 = (const float4*)g_wh;   // g_wh[0], g_wh[1] contiguous
        float4* wdst = (float4*)(sm + SM_B1H);
#pragma unroll
        for (int i = 0; i < 17; i++) {
            int v = i * NT + t;
            if (v < 2 * (WBYTES / 16)) wdst[v] = wsrc4[v];
        }
    }
    load_split_tile(sm + SM_AHI, sm + SM_ALO, efeat, e0, E, t);
    __syncthreads();

    int mq = w & 3, nq = w >> 2;
    uint32_t aoff = (uint32_t)((mq * 32 + (l & 15)) * 272 + (l >> 4) * 16);
    uint32_t boff = (uint32_t)((nq * 64 + ((l >> 4) & 1) * 8 + (l & 7)) * 272 + ((l >> 3) & 1) * 16);

    float acc[2][8][4];
#pragma unroll
    for (int i = 0; i < 2; i++)
#pragma unroll
        for (int j = 0; j < 8; j++)
#pragma unroll
            for (int q = 0; q < 4; q++) acc[i][j][q] = 0.f;

    // ---- GEMM1: efeat @ w_efeat^T (fp16x2) ----
    gemm_mma2(sb + SM_AHI + aoff, sb + SM_B1H + boff, acc);
    __syncthreads();   // A reads done before overwrite

    // ---- epilogue 1: gather node projections, SiLU, re-split into A buffers ----
    {
        char* ahi = sm + SM_AHI;
        char* alo = sm + SM_ALO;
        int cbase = nq * 64 + 2 * (l & 3);
        const float* p0 = g_proj[0];
        const float* p1 = g_proj[1];
#pragma unroll
        for (int mb = 0; mb < 2; mb++) {
#pragma unroll
            for (int h = 0; h < 2; h++) {
                int rr = mq * 32 + mb * 16 + (l >> 2) + h * 8;
                const float* ps = p0 + (size_t)sidx[rr] * KDIM;
                const float* pd = p1 + (size_t)didx[rr] * KDIM;
#pragma unroll
                for (int nb = 0; nb < 8; nb++) {
                    int c = cbase + nb * 8;
                    float2 s = *(const float2*)(ps + c);
                    float2 dd = *(const float2*)(pd + c);
                    float x0 = acc[mb][nb][2 * h + 0] + s.x + dd.x;
                    float x1 = acc[mb][nb][2 * h + 1] + s.y + dd.y;
                    float y0 = x0 * __fdividef(1.f, 1.f + __expf(-x0));
                    float y1 = x1 * __fdividef(1.f, 1.f + __expf(-x1));
                    uint32_t hi, lo;
                    split2(y0, y1, hi, lo);
                    uint32_t off = (uint32_t)rr * 272 + c * 2;
                    *(uint32_t*)(ahi + off) = hi;
                    *(uint32_t*)(alo + off) = lo;
                }
            }
        }
    }
    __syncthreads();

    // ---- GEMM2: silu @ w2^T (fp16x2) ----
#pragma unroll
    for (int i = 0; i < 2; i++)
#pragma unroll
        for (int j = 0; j < 8; j++)
#pragma unroll
            for (int q = 0; q < 4; q++) acc[i][j][q] = 0.f;
    gemm_mma2(sb + SM_AHI + aoff, sb + SM_B2H + boff, acc);

    // ---- epilogue 2: +b2, LayerNorm, store ----
    {
        const float* b2s = (const float*)(sm + SM_B2);
        const float* gs  = (const float*)(sm + SM_G);
        const float* bts = (const float*)(sm + SM_BT);
        int cbase = nq * 64 + 2 * (l & 3);
#pragma unroll
        for (int mb = 0; mb < 2; mb++) {
#pragma unroll
            for (int h = 0; h < 2; h++) {
                int rr = mq * 32 + mb * 16 + (l >> 2) + h * 8;
                int e = e0 + rr;
                float v[16];
                float sum = 0.f, ssq = 0.f;
#pragma unroll
                for (int nb = 0; nb < 8; nb++) {
                    int c = cbase + nb * 8;
                    float x0 = acc[mb][nb][2 * h + 0] + b2s[c];
                    float x1 = acc[mb][nb][2 * h + 1] + b2s[c + 1];
                    v[nb * 2 + 0] = x0; v[nb * 2 + 1] = x1;
                    sum += x0 + x1;
                    ssq += x0 * x0 + x1 * x1;
                }
                // reduce within quad (4 lanes cover one warp's 64-col half)
                sum += __shfl_xor_sync(0xffffffffu, sum, 1);
                ssq += __shfl_xor_sync(0xffffffffu, ssq, 1);
                sum += __shfl_xor_sync(0xffffffffu, sum, 2);
                ssq += __shfl_xor_sync(0xffffffffu, ssq, 2);
                // combine the two 64-col warp halves via static smem
                __shared__ float red[2][128][2];
                if ((l & 3) == 0) {
                    red[nq][rr][0] = sum;
                    red[nq][rr][1] = ssq;
                }
                __syncthreads();
                float tsum = red[0][rr][0] + red[1][rr][0];
                float tssq = red[0][rr][1] + red[1][rr][1];
                __syncthreads();
                float mu   = tsum * (1.f / 128.f);
                float var  = tssq * (1.f / 128.f) - mu * mu;
                float rstd = rsqrtf(var + 1e-5f);
                if (e < E) {
                    float* po = out + (size_t)e * KDIM;
#pragma unroll
                    for (int nb = 0; nb < 8; nb++) {
                        int c = cbase + nb * 8;
                        float2 o;
                        o.x = (v[nb * 2 + 0] - mu) * rstd * gs[c]     + bts[c];
                        o.y = (v[nb * 2 + 1] - mu) * rstd * gs[c + 1] + bts[c + 1];
                        *(float2*)(po + c) = o;
                    }
                }
            }
        }
    }
}

// ---------------- launch ----------------
extern "C" void kernel_launch(void* const* d_in, const int* in_sizes, int n_in,
                              void* d_out, int out_size) {
    const float* efeat    = (const float*)d_in[0];
    const float* src_feat = (const float*)d_in[1];
    const float* dst_feat = (const float*)d_in[2];
    const int*   src_idx  = (const int*)  d_in[3];
    const int*   dst_idx  = (const int*)  d_in[4];
    const float* w_efeat  = (const float*)d_in[5];
    const float* w_src    = (const float*)d_in[6];
    const float* w_dst    = (const float*)d_in[7];
    const float* b1       = (const float*)d_in[8];
    const float* w2       = (const float*)d_in[9];
    const float* b2       = (const float*)d_in[10];
    const float* ln_gamma = (const float*)d_in[11];
    const float* ln_beta  = (const float*)d_in[12];
    float* out = (float*)d_out;

    int E = in_sizes[3];
    int N = in_sizes[1] / KDIM;

    cudaFuncSetAttribute(node_kernel, cudaFuncAttributeMaxDynamicSharedMemorySize, NSM_TOTAL);
    cudaFuncSetAttribute(edge_kernel, cudaFuncAttributeMaxDynamicSharedMemorySize, SM_EDGE_TOTAL);

    // 1) fp16 weight images: 0=w_efeat 1=w2 2=w_src 3=w_dst
    wprep<<<4, 256>>>(w_efeat, w2, w_src, w_dst);

    // 2) node projections (b1 folded into dst branch)
    int node_grid = (N + TM - 1) / TM;
    node_kernel<<<node_grid, NT, NSM_TOTAL>>>(src_feat, nullptr, N, 0, 2);
    node_kernel<<<node_grid, NT, NSM_TOTAL>>>(dst_feat, b1,      N, 1, 3);

    // 3) fused edge pipeline (HMMA fp16x2)
    int edge_grid = (E + TM - 1) / TM;
    edge_kernel<<<edge_grid, NT, SM_EDGE_TOTAL>>>(efeat, src_idx, dst_idx,
                                                  b2, ln_gamma, ln_beta, out, E);
}

// round 17
// speedup vs baseline: 3.9085x; 1.1933x over previous
#include <cuda_runtime.h>
#include <cuda_fp16.h>
#include <stdint.h>

// ---------------- problem constants ----------------
#define KDIM 128
#define TM   128
#define NT   256
#define MAX_NODES 100000
#define WSTRIDE 136                      // fp16 elements per row (272 B)
#define WBYTES  (128 * WSTRIDE * 2)      // 34816 B per operand image
#define EDGE_GRID 304

extern __shared__ char dyn_smem[];

// ---------------- device scratch ----------------
__device__ float g_proj[2][MAX_NODES * KDIM];   // 0 = mlp_src, 1 = mlp_dst(+b1)
// fp16 padded [n][136] weight images: 0=w_efeat 1=w2 (contiguous), 2=w_src 3=w_dst
__device__ __align__(16) __half g_wh[4][128 * WSTRIDE];

// ---------------- mma helpers ----------------
__device__ __forceinline__ uint32_t smem_to_u32(const void* p) {
    uint32_t a;
    asm("{ .reg .u64 t; cvta.to.shared.u64 t, %1; cvt.u32.u64 %0, t; }" : "=r"(a) : "l"(p));
    return a;
}
__device__ __forceinline__ void ldsm_x4(uint32_t* r, uint32_t addr) {
    asm volatile("ldmatrix.sync.aligned.m8n8.x4.shared.b16 {%0,%1,%2,%3}, [%4];"
                 : "=r"(r[0]), "=r"(r[1]), "=r"(r[2]), "=r"(r[3]) : "r"(addr));
}
__device__ __forceinline__ void mma_f16(float* d, const uint32_t* a, const uint32_t* b) {
    asm volatile("mma.sync.aligned.m16n8k16.row.col.f32.f16.f16.f32 "
                 "{%0,%1,%2,%3}, {%4,%5,%6,%7}, {%8,%9}, {%0,%1,%2,%3};"
                 : "+f"(d[0]), "+f"(d[1]), "+f"(d[2]), "+f"(d[3])
                 : "r"(a[0]), "r"(a[1]), "r"(a[2]), "r"(a[3]), "r"(b[0]), "r"(b[1]));
}
__device__ __forceinline__ uint32_t pack_h2(__half a, __half b) {
    return (uint32_t)__half_as_ushort(a) | ((uint32_t)__half_as_ushort(b) << 16);
}
__device__ __forceinline__ void split2(float x0, float x1, uint32_t &hi, uint32_t &lo) {
    __half h0 = __float2half_rn(x0), h1 = __float2half_rn(x1);
    __half l0 = __float2half_rn(x0 - __half2float(h0));
    __half l1 = __float2half_rn(x1 - __half2float(h1));
    hi = pack_h2(h0, h1);
    lo = pack_h2(l0, l1);
}

// ---------------- weight prep ----------------
__global__ void wprep(const float* __restrict__ wef, const float* __restrict__ w2,
                      const float* __restrict__ wsrc, const float* __restrict__ wdst) {
    const float* w = (blockIdx.x == 0) ? wef : (blockIdx.x == 1) ? w2
                   : (blockIdx.x == 2) ? wsrc : wdst;
    __half* hi = g_wh[blockIdx.x];
    for (int v = threadIdx.x; v < 128 * WSTRIDE; v += blockDim.x) {
        int n = v / WSTRIDE, k = v % WSTRIDE;
        float x = (k < 128) ? w[n * 128 + k] : 0.f;
        hi[v] = __float2half_rn(x);
    }
}

// ---------------- fp16x2 GEMM core (warp: 32 rows x 64 cols) ----------------
__device__ __forceinline__ void gemm_mma2(uint32_t aHi, uint32_t bHi, float acc[2][8][4]) {
#pragma unroll
    for (int k = 0; k < 8; k++) {
        uint32_t af[2][2][4];
        uint32_t bf[8][2];
#pragma unroll
        for (int mb = 0; mb < 2; mb++) {
            ldsm_x4(af[0][mb], aHi +          mb * (16 * 272) + k * 32);
            ldsm_x4(af[1][mb], aHi + WBYTES + mb * (16 * 272) + k * 32);
        }
#pragma unroll
        for (int p = 0; p < 4; p++)
            ldsm_x4(&bf[2 * p][0], bHi + p * (16 * 272) + k * 32);
#pragma unroll
        for (int mb = 0; mb < 2; mb++)
#pragma unroll
            for (int nb = 0; nb < 8; nb++) {
                mma_f16(acc[mb][nb], af[0][mb], bf[nb]);
                mma_f16(acc[mb][nb], af[1][mb], bf[nb]);
            }
    }
}

// load a [128 x 128] fp32 row tile, split fp16 hi/lo into padded smem images
__device__ __forceinline__ void load_split_tile(char* ahi, char* alo,
                                                const float* __restrict__ feat,
                                                int base, int limit, int t) {
#pragma unroll
    for (int i = 0; i < 16; i++) {
        int idx = i * NT + t;
        int row = idx >> 5, c4 = idx & 31;
        float4 v = make_float4(0.f, 0.f, 0.f, 0.f);
        if (base + row < limit)
            v = *(const float4*)(feat + (size_t)(base + row) * KDIM + c4 * 4);
        uint32_t h0, l0, h1, l1;
        split2(v.x, v.y, h0, l0);
        split2(v.z, v.w, h1, l1);
        uint32_t off = (uint32_t)row * 272 + c4 * 8;
        *(uint32_t*)(ahi + off)     = h0;
        *(uint32_t*)(ahi + off + 4) = h1;
        *(uint32_t*)(alo + off)     = l0;
        *(uint32_t*)(alo + off + 4) = l1;
    }
}

// issue gather loads for one tile into registers (consumed in epilogue-1)
__device__ __forceinline__ void gather_issue(const int* __restrict__ srcidx,
                                             const int* __restrict__ dstidx,
                                             int e0, int E, int mq, int l, int cbase,
                                             float2 sg[4][8], float2 dg[4][8]) {
    const float* p0 = g_proj[0];
    const float* p1 = g_proj[1];
#pragma unroll
    for (int r4 = 0; r4 < 4; r4++) {
        int rr = mq * 32 + (r4 >> 1) * 16 + (l >> 2) + (r4 & 1) * 8;
        int e = e0 + rr;
        int ee = (e < E) ? e : (E - 1);
        int is = __ldg(srcidx + ee), id = __ldg(dstidx + ee);
        const float* ps = p0 + (size_t)is * KDIM + cbase;
        const float* pd = p1 + (size_t)id * KDIM + cbase;
#pragma unroll
        for (int nb = 0; nb < 8; nb++) {
            sg[r4][nb] = *(const float2*)(ps + nb * 8);
            dg[r4][nb] = *(const float2*)(pd + nb * 8);
        }
    }
}

// ---------------- node projection kernel (HMMA fp16x2, unchanged) ----------------
#define NSM_TOTAL (3 * WBYTES)

__global__ void __launch_bounds__(NT)
node_kernel(const float* __restrict__ feat, const float* __restrict__ bias,
            int N, int which, int wsel) {
    char* sm = dyn_smem;
    uint32_t sb = smem_to_u32(sm);
    int t = threadIdx.x, w = t >> 5, l = t & 31;
    int n0 = blockIdx.x * TM;

    {
        const float4* wsrc4 = (const float4*)g_wh[wsel];
        float4* wdst = (float4*)(sm + 2 * WBYTES);
#pragma unroll
        for (int i = 0; i < 9; i++) {
            int v = i * NT + t;
            if (v < WBYTES / 16) wdst[v] = wsrc4[v];
        }
    }
    load_split_tile(sm, sm + WBYTES, feat, n0, N, t);
    __syncthreads();

    int mq = w & 3, nq = w >> 2;
    uint32_t aoff = (uint32_t)((mq * 32 + (l & 15)) * 272 + (l >> 4) * 16);
    uint32_t boff = (uint32_t)((nq * 64 + ((l >> 4) & 1) * 8 + (l & 7)) * 272 + ((l >> 3) & 1) * 16);

    float acc[2][8][4];
#pragma unroll
    for (int i = 0; i < 2; i++)
#pragma unroll
        for (int j = 0; j < 8; j++)
#pragma unroll
            for (int q = 0; q < 4; q++) acc[i][j][q] = 0.f;

    gemm_mma2(sb + aoff, sb + 2 * WBYTES + boff, acc);

    float* outp = g_proj[which];
    int cbase = nq * 64 + 2 * (l & 3);
#pragma unroll
    for (int mb = 0; mb < 2; mb++) {
#pragma unroll
        for (int h = 0; h < 2; h++) {
            int rr = mq * 32 + mb * 16 + (l >> 2) + h * 8;
            int m = n0 + rr;
            if (m < N) {
                float* po = outp + (size_t)m * KDIM;
#pragma unroll
                for (int nb = 0; nb < 8; nb++) {
                    int c = cbase + nb * 8;
                    float b0 = bias ? __ldg(bias + c)      : 0.f;
                    float b1v = bias ? __ldg(bias + c + 1) : 0.f;
                    float2 o;
                    o.x = acc[mb][nb][2 * h + 0] + b0;
                    o.y = acc[mb][nb][2 * h + 1] + b1v;
                    *(float2*)(po + c) = o;
                }
            }
        }
    }
}

// ---------------- persistent fused edge kernel ----------------
// smem: header (b2/gamma/beta/red) + A hi/lo + B1 + B2
#define SM_B2   0
#define SM_G    512
#define SM_BT   1024
#define SM_RED  2048                      // float[2][128][2] = 2048 B
#define SM_AHI  4096
#define SM_ALO  (SM_AHI + WBYTES)
#define SM_B1H  (SM_ALO + WBYTES)
#define SM_B2H  (SM_B1H + WBYTES)
#define SM_EDGE_TOTAL (SM_B2H + WBYTES)   // 143360 B

__global__ void __launch_bounds__(NT)
edge_kernel(const float* __restrict__ efeat,
            const int* __restrict__ srcidx, const int* __restrict__ dstidx,
            const float* __restrict__ b2, const float* __restrict__ gamma,
            const float* __restrict__ beta,
            float* __restrict__ out, int E) {
    char* sm = dyn_smem;
    uint32_t sb = smem_to_u32(sm);
    int t = threadIdx.x, w = t >> 5, l = t & 31;
    int mq = w & 3, nq = w >> 2;
    int ntiles = (E + TM - 1) / TM;

    // ---- one-time CTA setup: weights + vectors ----
    {
        const float4* wsrc4 = (const float4*)g_wh;     // g_wh[0], g_wh[1] contiguous
        float4* wdst = (float4*)(sm + SM_B1H);
#pragma unroll
        for (int i = 0; i < 17; i++) {
            int v = i * NT + t;
            if (v < 2 * (WBYTES / 16)) wdst[v] = wsrc4[v];
        }
    }
    if (t < KDIM) {
        ((float*)(sm + SM_B2))[t] = b2[t];
        ((float*)(sm + SM_G ))[t] = gamma[t];
        ((float*)(sm + SM_BT))[t] = beta[t];
    }

    int cbase = nq * 64 + 2 * (l & 3);
    uint32_t aoff = (uint32_t)((mq * 32 + (l & 15)) * 272 + (l >> 4) * 16);
    uint32_t boff = (uint32_t)((nq * 64 + ((l >> 4) & 1) * 8 + (l & 7)) * 272 + ((l >> 3) & 1) * 16);

    float2 sg[4][8], dg[4][8];
    int tile = blockIdx.x;
    if (tile < ntiles) {
        load_split_tile(sm + SM_AHI, sm + SM_ALO, efeat, tile * TM, E, t);
        gather_issue(srcidx, dstidx, tile * TM, E, mq, l, cbase, sg, dg);
    }
    __syncthreads();

    float* red = (float*)(sm + SM_RED);
    const float* b2s = (const float*)(sm + SM_B2);
    const float* gs  = (const float*)(sm + SM_G);
    const float* bts = (const float*)(sm + SM_BT);

    for (; tile < ntiles; tile += gridDim.x) {
        int e0 = tile * TM;
        int tnext = tile + gridDim.x;

        // ---- GEMM1: efeat @ w_efeat^T ----
        float acc[2][8][4];
#pragma unroll
        for (int i = 0; i < 2; i++)
#pragma unroll
            for (int j = 0; j < 8; j++)
#pragma unroll
                for (int q = 0; q < 4; q++) acc[i][j][q] = 0.f;
        gemm_mma2(sb + SM_AHI + aoff, sb + SM_B1H + boff, acc);
        __syncthreads();   // all warps finished reading A before overwrite

        // ---- epilogue 1: +prefetched gathers, SiLU, re-split in place ----
        {
            char* ahi = sm + SM_AHI;
            char* alo = sm + SM_ALO;
#pragma unroll
            for (int mb = 0; mb < 2; mb++) {
#pragma unroll
                for (int h = 0; h < 2; h++) {
                    int r4 = mb * 2 + h;
                    int rr = mq * 32 + mb * 16 + (l >> 2) + h * 8;
#pragma unroll
                    for (int nb = 0; nb < 8; nb++) {
                        int c = cbase + nb * 8;
                        float x0 = acc[mb][nb][2 * h + 0] + sg[r4][nb].x + dg[r4][nb].x;
                        float x1 = acc[mb][nb][2 * h + 1] + sg[r4][nb].y + dg[r4][nb].y;
                        float y0 = x0 * __fdividef(1.f, 1.f + __expf(-x0));
                        float y1 = x1 * __fdividef(1.f, 1.f + __expf(-x1));
                        uint32_t hi, lo;
                        split2(y0, y1, hi, lo);
                        uint32_t off = (uint32_t)rr * 272 + c * 2;
                        *(uint32_t*)(ahi + off) = hi;
                        *(uint32_t*)(alo + off) = lo;
                    }
                }
            }
        }
        __syncthreads();   // silu tile visible

        // ---- GEMM2: silu @ w2^T ----
#pragma unroll
        for (int i = 0; i < 2; i++)
#pragma unroll
            for (int j = 0; j < 8; j++)
#pragma unroll
                for (int q = 0; q < 4; q++) acc[i][j][q] = 0.f;
        gemm_mma2(sb + SM_AHI + aoff, sb + SM_B2H + boff, acc);
        __syncthreads();   // A free

        // ---- prefetch next tile: efeat split + gathers (hidden under epilogue 2) ----
        if (tnext < ntiles) {
            load_split_tile(sm + SM_AHI, sm + SM_ALO, efeat, tnext * TM, E, t);
            gather_issue(srcidx, dstidx, tnext * TM, E, mq, l, cbase, sg, dg);
        }

        // ---- epilogue 2: +b2, LayerNorm (single reduction round), store ----
        // pass 1: per-row sums
#pragma unroll
        for (int mb = 0; mb < 2; mb++) {
#pragma unroll
            for (int h = 0; h < 2; h++) {
                int rr = mq * 32 + mb * 16 + (l >> 2) + h * 8;
                float sum = 0.f, ssq = 0.f;
#pragma unroll
                for (int nb = 0; nb < 8; nb++) {
                    int c = cbase + nb * 8;
                    float x0 = acc[mb][nb][2 * h + 0] + b2s[c];
                    float x1 = acc[mb][nb][2 * h + 1] + b2s[c + 1];
                    sum += x0 + x1;
                    ssq += x0 * x0 + x1 * x1;
                }
                sum += __shfl_xor_sync(0xffffffffu, sum, 1);
                ssq += __shfl_xor_sync(0xffffffffu, ssq, 1);
                sum += __shfl_xor_sync(0xffffffffu, sum, 2);
                ssq += __shfl_xor_sync(0xffffffffu, ssq, 2);
                if ((l & 3) == 0) {
                    red[(nq * 128 + rr) * 2 + 0] = sum;
                    red[(nq * 128 + rr) * 2 + 1] = ssq;
                }
            }
        }
        __syncthreads();   // also publishes next-tile A split for next GEMM1
        // pass 2: normalize + store (recompute values from live acc)
#pragma unroll
        for (int mb = 0; mb < 2; mb++) {
#pragma unroll
            for (int h = 0; h < 2; h++) {
                int rr = mq * 32 + mb * 16 + (l >> 2) + h * 8;
                int e = e0 + rr;
                float tsum = red[rr * 2 + 0] + red[(128 + rr) * 2 + 0];
                float tssq = red[rr * 2 + 1] + red[(128 + rr) * 2 + 1];
                float mu   = tsum * (1.f / 128.f);
                float var  = tssq * (1.f / 128.f) - mu * mu;
                float rstd = rsqrtf(var + 1e-5f);
                if (e < E) {
                    float* po = out + (size_t)e * KDIM;
#pragma unroll
                    for (int nb = 0; nb < 8; nb++) {
                        int c = cbase + nb * 8;
                        float x0 = acc[mb][nb][2 * h + 0] + b2s[c];
                        float x1 = acc[mb][nb][2 * h + 1] + b2s[c + 1];
                        float2 o;
                        o.x = (x0 - mu) * rstd * gs[c]     + bts[c];
                        o.y = (x1 - mu) * rstd * gs[c + 1] + bts[c + 1];
                        *(float2*)(po + c) = o;
                    }
                }
            }
        }
        // no trailing sync needed: next iteration's post-GEMM1 sync orders
        // red reuse and A overwrite.
    }
}

// ---------------- launch ----------------
extern "C" void kernel_launch(void* const* d_in, const int* in_sizes, int n_in,
                              void* d_out, int out_size) {
    const float* efeat    = (const float*)d_in[0];
    const float* src_feat = (const float*)d_in[1];
    const float* dst_feat = (const float*)d_in[2];
    const int*   src_idx  = (const int*)  d_in[3];
    const int*   dst_idx  = (const int*)  d_in[4];
    const float* w_efeat  = (const float*)d_in[5];
    const float* w_src    = (const float*)d_in[6];
    const float* w_dst    = (const float*)d_in[7];
    const float* b1       = (const float*)d_in[8];
    const float* w2       = (const float*)d_in[9];
    const float* b2       = (const float*)d_in[10];
    const float* ln_gamma = (const float*)d_in[11];
    const float* ln_beta  = (const float*)d_in[12];
    float* out = (float*)d_out;

    int E = in_sizes[3];
    int N = in_sizes[1] / KDIM;

    cudaFuncSetAttribute(node_kernel, cudaFuncAttributeMaxDynamicSharedMemorySize, NSM_TOTAL);
    cudaFuncSetAttribute(edge_kernel, cudaFuncAttributeMaxDynamicSharedMemorySize, SM_EDGE_TOTAL);

    // 1) fp16 weight images: 0=w_efeat 1=w2 2=w_src 3=w_dst
    wprep<<<4, 256>>>(w_efeat, w2, w_src, w_dst);

    // 2) node projections (b1 folded into dst branch)
    int node_grid = (N + TM - 1) / TM;
    node_kernel<<<node_grid, NT, NSM_TOTAL>>>(src_feat, nullptr, N, 0, 2);
    node_kernel<<<node_grid, NT, NSM_TOTAL>>>(dst_feat, b1,      N, 1, 3);

    // 3) persistent fused edge pipeline
    edge_kernel<<<EDGE_GRID, NT, SM_EDGE_TOTAL>>>(efeat, src_idx, dst_idx,
                                                  b2, ln_gamma, ln_beta, out, E);
}